// round 13
// baseline (speedup 1.0000x reference)
#include <cuda_runtime.h>
#include <cuda_fp16.h>
#include <math.h>
#include <stdint.h>

// Problem constants
#define BATCH   16
#define LSEQ    4096
#define DDIM    128
#define HDIM    256
#define KA      255
#define KOUT    256
#define LCHUNK  64
#define NCHUNK  64
#define MASKVAL -1e30f

// ---------------- device scratch (no allocation allowed) --------------------
__device__ float  g_partS0[BATCH * NCHUNK * 256];
__device__ float  g_partS1[BATCH * NCHUNK * 256];
__device__ float4 g_params4[BATCH * KA * 2];
// fp16 B-fragment images, PAIRED tiles (one LDS.128 = 2 tiles):
__device__ __align__(16) uint2 g_W1h[8192];     // 128 pairs x 64 = 64KB
__device__ __align__(16) uint2 g_W2h[16384];    // 256 pairs x 64 = 128KB

// ---------------- helpers ----------------------------------------------------
__device__ __forceinline__ uint32_t smem_u32(const void* p) {
    uint32_t a;
    asm("{ .reg .u64 t; cvta.to.shared.u64 t, %1; cvt.u32.u64 %0, t; }"
        : "=r"(a) : "l"(p));
    return a;
}
__device__ __forceinline__ void cp16(uint32_t dst, const void* src) {
    asm volatile("cp.async.cg.shared.global [%0], [%1], 16;"
                 :: "r"(dst), "l"(src) : "memory");
}
#define CP_COMMIT() asm volatile("cp.async.commit_group;" ::: "memory")
#define CP_WAIT0()  asm volatile("cp.async.wait_group 0;" ::: "memory")

__device__ __forceinline__ uint32_t hfpack(float a, float b) {
    __half ha = __float2half_rn(a);
    __half hb = __float2half_rn(b);
    return (uint32_t)__half_as_ushort(ha) |
           ((uint32_t)__half_as_ushort(hb) << 16);
}
__device__ __forceinline__ void mma_f16(float* c, const uint4& a,
                                        uint32_t b0, uint32_t b1) {
    asm volatile(
        "mma.sync.aligned.m16n8k16.row.col.f32.f16.f16.f32 "
        "{%0,%1,%2,%3}, {%4,%5,%6,%7}, {%8,%9}, {%0,%1,%2,%3};"
        : "+f"(c[0]), "+f"(c[1]), "+f"(c[2]), "+f"(c[3])
        : "r"(a.x), "r"(a.y), "r"(a.z), "r"(a.w), "r"(b0), "r"(b1));
}
__device__ __forceinline__ float ftanh(float x) {
    float e = __expf(2.f * x);
    return 1.f - __fdividef(2.f, e + 1.f);
}

// =============================================================================
// K0: fp16 B images with PAIRED tile layout: pair P at uint2 index
// P*64 + t*2 + half  ->  lane t's LDS.128 returns {tile 2P (xy), tile 2P+1 (zw)}.
// W1 pairs: kt*16 + p (p = ntG/2).  W2 pairs: c*64 + kt*4 + p (p within chunk).
// =============================================================================
__global__ void k0_prep(const float* __restrict__ W1, const float* __restrict__ W2)
{
    int g = blockIdx.x * 256 + threadIdx.x;
    if (g < 8192) {                 // W1 [128][256]
        int i1 = g >> 5, t = g & 31;
        int kt = i1 >> 5, ntG = i1 & 31;
        int n = ntG * 8 + (t >> 2);
        int k = kt * 16 + (t & 3) * 2;
        uint2 r;
        r.x = hfpack(W1[k * 256 + n],       W1[(k + 1) * 256 + n]);
        r.y = hfpack(W1[(k + 8) * 256 + n], W1[(k + 9) * 256 + n]);
        int p = ntG >> 1, half = ntG & 1;
        g_W1h[(kt * 16 + p) * 64 + t * 2 + half] = r;
    } else if (g < 8192 + 16384) {  // W2 [256][255] -> padded to 256 cols
        int g2 = g - 8192;
        int i2 = g2 >> 5, t = g2 & 31;
        int c = i2 >> 7, rem = i2 & 127;          // 64-col chunk c
        int kt = rem >> 3, nt = rem & 7;
        int n = c * 64 + nt * 8 + (t >> 2);
        int k = kt * 16 + (t & 3) * 2;
        float v0 = 0.f, v1 = 0.f, v2 = 0.f, v3 = 0.f;
        if (n < KA) {
            v0 = W2[k * KA + n];
            v1 = W2[(k + 1) * KA + n];
            v2 = W2[(k + 8) * KA + n];
            v3 = W2[(k + 9) * KA + n];
        }
        uint2 r;
        r.x = hfpack(v0, v1);
        r.y = hfpack(v2, v3);
        int p = nt >> 1, half = nt & 1;
        g_W2h[(c * 64 + kt * 4 + p) * 64 + t * 2 + half] = r;
    }
}

// dummy kernel: positions k1 at ncu's captured launch index (3)
__global__ void k_dummy() {}

// ---------------- K1 smem byte map (64-row chunk; ~101KB -> 2 blocks/SM) -----
// phase1: Xs single-term [0,16K), W1 B-frags [16K,80K)
// phase2: A2 single-term [0,32K) (aliases Xs), W2 double buffer 2x32KB [32K,96K)
#define X_OFF    0
#define W1_OFF   16384
#define A2_OFF   0
#define W2_OFF   32768
#define RS_B     98304
#define MS_B     98560
#define BS_B     98816
#define PART_B   99840
#define SMEM_K1  108032

// =============================================================================
// K1: 64-row L-chunks, 1024 blocks, 2 blocks/SM.
//   GEMM1: A=X fp16 single term, B=W1 fp16 paired LDS.128.
//   GEMM2: each warp holds its full A2 slice (16 x uint4) IN REGISTERS across
//   all 4 chunks (A2 smem re-reads eliminated); B=W2 paired LDS.128.
// =============================================================================
__global__ __launch_bounds__(256, 2)
void k1_attn(const float* __restrict__ X, const float* __restrict__ mask,
             const float* __restrict__ b1, const float* __restrict__ Wr)
{
    extern __shared__ char smc[];
    uint4*  Xs   = (uint4*)(smc + X_OFF);
    uint4*  W1s4 = (uint4*)(smc + W1_OFF);
    uint4*  A2s  = (uint4*)(smc + A2_OFF);
    float*  rsm  = (float*)(smc + RS_B);
    float*  msm  = (float*)(smc + MS_B);
    float*  bsm  = (float*)(smc + BS_B);
    float2* part = (float2*)(smc + PART_B);   // [4 warpM][256 cols]

    const uint32_t sb  = smem_u32(smc);
    const int tid = threadIdx.x;
    const int wid = tid >> 5;
    const int t   = tid & 31;
    const int b     = blockIdx.y;
    const int chunk = blockIdx.x;
    const int l0    = chunk * LCHUNK;

    const float* Xg = X + ((size_t)b * LSEQ + l0) * DDIM;

    // ---- issue W1 image copy (64KB) async; overlap with X staging ----
    {
        uint32_t dst = sb + W1_OFF;
        #pragma unroll
        for (int i = 0; i < 16; ++i)
            cp16(dst + (tid + i * 256) * 16, (const uint4*)g_W1h + tid + i * 256);
        CP_COMMIT();
    }

    // ---- stage X as single-term fp16 A-frags: 2 warps per m-tile ----
    {
        int mtile = wid >> 1;          // 4 m-tiles of 16 rows
        int khalf = wid & 1;
        int r0 = mtile * 16 + (t >> 2);
        const float* xr0 = Xg + r0 * DDIM;
        const float* xr1 = Xg + (r0 + 8) * DDIM;
        #pragma unroll
        for (int kq = 0; kq < 4; ++kq) {
            int kt = khalf * 4 + kq;
            int k0 = kt * 16 + (t & 3) * 2;
            float2 v00 = *(const float2*)(xr0 + k0);
            float2 v10 = *(const float2*)(xr1 + k0);
            float2 v01 = *(const float2*)(xr0 + k0 + 8);
            float2 v11 = *(const float2*)(xr1 + k0 + 8);
            uint4 hi;
            hi.x = hfpack(v00.x, v00.y);
            hi.y = hfpack(v10.x, v10.y);
            hi.z = hfpack(v01.x, v01.y);
            hi.w = hfpack(v11.x, v11.y);
            Xs[(mtile * 8 + kt) * 32 + t] = hi;
        }
    }

    // ---- small loads: rs = X.Wr, mask, b1 ----
    if (tid < 64) {
        float s0 = 0.f, s1 = 0.f, s2 = 0.f, s3 = 0.f;
        const float4* xr = (const float4*)(Xg + tid * DDIM);
        const float4* wr = (const float4*)Wr;
        #pragma unroll 8
        for (int d = 0; d < 32; ++d) {
            float4 xv = xr[d], wv = wr[d];
            s0 = fmaf(xv.x, wv.x, s0);
            s1 = fmaf(xv.y, wv.y, s1);
            s2 = fmaf(xv.z, wv.z, s2);
            s3 = fmaf(xv.w, wv.w, s3);
        }
        rsm[tid] = (s0 + s1) + (s2 + s3);
        msm[tid] = mask[(size_t)b * LSEQ + l0 + tid];
    }
    bsm[tid] = b1[tid];
    CP_WAIT0();
    __syncthreads();

    // GEMM1 layout: 2 m-groups of 2 m-tiles, 4 n-groups of 8 n-tiles (4 pairs)
    const int warpM1 = wid & 1;
    const int warpN1 = wid >> 1;

    // ---- GEMM1: acc[mt][nt][4] = X @ W1, paired-B LDS.128 ----
    float acc[2][8][4];
    #pragma unroll
    for (int mt = 0; mt < 2; ++mt)
        #pragma unroll
        for (int nt = 0; nt < 8; ++nt)
            #pragma unroll
            for (int q = 0; q < 4; ++q) acc[mt][nt][q] = 0.f;

    #pragma unroll 1
    for (int kt = 0; kt < 8; ++kt) {
        uint4 ah[2];
        #pragma unroll
        for (int mt = 0; mt < 2; ++mt) {
            int mtG = warpM1 * 2 + mt;
            ah[mt] = Xs[(mtG * 8 + kt) * 32 + t];
        }
        #pragma unroll
        for (int pp = 0; pp < 4; ++pp) {
            uint4 bb = W1s4[(kt * 16 + warpN1 * 4 + pp) * 32 + t];
            #pragma unroll
            for (int mt = 0; mt < 2; ++mt) {
                mma_f16(acc[mt][pp * 2 + 0], ah[mt], bb.x, bb.y);
                mma_f16(acc[mt][pp * 2 + 1], ah[mt], bb.z, bb.w);
            }
        }
    }
    __syncthreads();   // all warps done reading X/W1

    // ---- prefetch W2 chunk 0 (32KB) into buf0; overlaps tanh epilogue ----
    {
        uint32_t dst = sb + W2_OFF;
        #pragma unroll
        for (int i = 0; i < 8; ++i)
            cp16(dst + (tid + i * 256) * 16, (const uint4*)g_W2h + tid + i * 256);
        CP_COMMIT();
    }

    // ---- epilogue 1: T = tanh(acc + b1) -> single fp16 term -> A2 frags ----
    #pragma unroll
    for (int mt = 0; mt < 2; ++mt) {
        int mtG = warpM1 * 2 + mt;
        #pragma unroll
        for (int j = 0; j < 4; ++j) {
            int nt0 = 2 * j, nt1 = 2 * j + 1;
            int c0 = (warpN1 * 8 + nt0) * 8 + (t & 3) * 2;
            int c1 = (warpN1 * 8 + nt1) * 8 + (t & 3) * 2;
            float b00 = bsm[c0], b01 = bsm[c0 + 1];
            float b10 = bsm[c1], b11 = bsm[c1 + 1];
            uint4 hi;
            hi.x = hfpack(ftanh(acc[mt][nt0][0] + b00), ftanh(acc[mt][nt0][1] + b01));
            hi.y = hfpack(ftanh(acc[mt][nt0][2] + b00), ftanh(acc[mt][nt0][3] + b01));
            hi.z = hfpack(ftanh(acc[mt][nt1][0] + b10), ftanh(acc[mt][nt1][1] + b11));
            hi.w = hfpack(ftanh(acc[mt][nt1][2] + b10), ftanh(acc[mt][nt1][3] + b11));
            int ktG = warpN1 * 4 + j;
            A2s[(mtG * 16 + ktG) * 32 + t] = hi;
        }
    }

    // GEMM2 layout: 4 m-groups of 1 m-tile, 2 n-groups of 4 n-tiles (2 pairs)
    const int warpM = wid & 3;     // mtG
    const int warpN = wid >> 2;    // 0..1

    const float mv0 = msm[warpM * 16 + (t >> 2)];
    const float mv1 = msm[warpM * 16 + (t >> 2) + 8];
    const float rw0 = rsm[warpM * 16 + (t >> 2)];
    const float rw1 = rsm[warpM * 16 + (t >> 2) + 8];

    CP_WAIT0();
    __syncthreads();   // chunk-0 W2 staged AND A2 writes visible

    // ---- load this warp's FULL A2 slice into registers (held across chunks) --
    uint4 ah2[16];
    #pragma unroll
    for (int kt = 0; kt < 16; ++kt)
        ah2[kt] = A2s[(warpM * 16 + kt) * 32 + t];

    #pragma unroll 1
    for (int c = 0; c < 4; ++c) {
        if (c > 0) {
            CP_WAIT0();
            __syncthreads();   // buf[c&1] staged; prev chunk reads done
        }

        // prefetch chunk c+1 into the other buffer (hidden under mma below)
        if (c < 3) {
            uint32_t dst = sb + W2_OFF + ((c + 1) & 1) * 32768;
            const uint4* src = (const uint4*)g_W2h + (c + 1) * 2048;
            #pragma unroll
            for (int i = 0; i < 8; ++i)
                cp16(dst + (tid + i * 256) * 16, src + tid + i * 256);
            CP_COMMIT();
        }

        const uint4* W2s4 = (const uint4*)(smc + W2_OFF + (c & 1) * 32768);

        float acc2[4][4];
        #pragma unroll
        for (int nt = 0; nt < 4; ++nt)
            #pragma unroll
            for (int q = 0; q < 4; ++q) acc2[nt][q] = 0.f;

        #pragma unroll 4
        for (int kt = 0; kt < 16; ++kt) {
            #pragma unroll
            for (int ntp = 0; ntp < 2; ++ntp) {
                uint4 bb = W2s4[(kt * 4 + warpN * 2 + ntp) * 32 + t];
                mma_f16(acc2[ntp * 2 + 0], ah2[kt], bb.x, bb.y);
                mma_f16(acc2[ntp * 2 + 1], ah2[kt], bb.z, bb.w);
            }
        }

        // per-chunk epilogue: e = exp(masked logit); column sums over 16 rows
        #pragma unroll
        for (int nt = 0; nt < 4; ++nt) {
            float e0 = __expf(mv0 * acc2[nt][0] + (1.f - mv0) * MASKVAL);
            float e1 = __expf(mv0 * acc2[nt][1] + (1.f - mv0) * MASKVAL);
            float e2 = __expf(mv1 * acc2[nt][2] + (1.f - mv1) * MASKVAL);
            float e3 = __expf(mv1 * acc2[nt][3] + (1.f - mv1) * MASKVAL);
            float s0A = e0 + e2;
            float s0B = e1 + e3;
            float s1A = fmaf(e0, rw0, e2 * rw1);
            float s1B = fmaf(e1, rw0, e3 * rw1);
            #pragma unroll
            for (int o = 4; o < 32; o <<= 1) {
                s0A += __shfl_xor_sync(0xffffffffu, s0A, o);
                s0B += __shfl_xor_sync(0xffffffffu, s0B, o);
                s1A += __shfl_xor_sync(0xffffffffu, s1A, o);
                s1B += __shfl_xor_sync(0xffffffffu, s1B, o);
            }
            if (t < 4) {
                int col = c * 64 + (warpN * 4 + nt) * 8 + t * 2;
                part[warpM * 256 + col]     = make_float2(s0A, s1A);
                part[warpM * 256 + col + 1] = make_float2(s0B, s1B);
            }
        }
    }
    __syncthreads();

    // ---- final cross-warp column reduce -> global partials ----
    {
        float2 p0 = part[tid];
        float2 p1 = part[256 + tid];
        float2 p2 = part[512 + tid];
        float2 p3 = part[768 + tid];
        size_t idx = ((size_t)b * NCHUNK + chunk) * 256 + tid;
        g_partS0[idx] = (p0.x + p1.x) + (p2.x + p3.x);
        g_partS1[idx] = (p0.y + p1.y) + (p2.y + p3.y);
    }
}

// =============================================================================
// K23: per batch: reduce chunk partials -> mu; softmax+cumsum -> cdf params
// =============================================================================
__global__ void k23(const float* __restrict__ br)
{
    __shared__ float sm_mu[256];
    __shared__ float ws[8];
    __shared__ float bc[2];
    int b = blockIdx.x, tI = threadIdx.x;
    int lane = tI & 31, warp = tI >> 5;

    float s0 = 0.f, s1 = 0.f;
    #pragma unroll 4
    for (int c = 0; c < NCHUNK; ++c) {
        size_t idx = ((size_t)b * NCHUNK + c) * 256 + tI;
        s0 += g_partS0[idx];
        s1 += g_partS1[idx];
    }
    sm_mu[tI] = s1 / s0 + br[0];
    __syncthreads();

    float e = (tI == 0) ? 0.f : sm_mu[tI - 1];

    float m = e;
    #pragma unroll
    for (int o = 16; o; o >>= 1) m = fmaxf(m, __shfl_xor_sync(0xffffffffu, m, o));
    if (lane == 0) ws[warp] = m;
    __syncthreads();
    if (tI < 8) {
        float v = ws[tI];
        #pragma unroll
        for (int o = 4; o; o >>= 1) v = fmaxf(v, __shfl_xor_sync(0xffu, v, o));
        if (tI == 0) bc[0] = v;
    }
    __syncthreads();
    float M = bc[0];

    float p = expf(e - M);
    float s = p;
    #pragma unroll
    for (int o = 16; o; o >>= 1) s += __shfl_xor_sync(0xffffffffu, s, o);
    if (lane == 0) ws[warp] = s;
    __syncthreads();
    if (tI < 8) {
        float v = ws[tI];
        #pragma unroll
        for (int o = 4; o; o >>= 1) v += __shfl_xor_sync(0xffu, v, o);
        if (tI == 0) bc[1] = v;
    }
    __syncthreads();
    p /= bc[1];

    float v = p;
    #pragma unroll
    for (int o = 1; o < 32; o <<= 1) {
        float u = __shfl_up_sync(0xffffffffu, v, o);
        if (lane >= o) v += u;
    }
    if (lane == 31) ws[warp] = v;
    __syncthreads();
    if (warp == 0 && lane < 8) {
        float w = ws[lane];
        #pragma unroll
        for (int o = 1; o < 8; o <<= 1) {
            float u = __shfl_up_sync(0xffu, w, o);
            if (lane >= o) w += u;
        }
        ws[lane] = w;
    }
    __syncthreads();
    float cum = v + (warp ? ws[warp - 1] : 0.f);

    if (tI < KA) {
        float mode = fminf(fmaxf(cum, 1e-4f), 0.9999f);
        float a  = fminf(fmaxf(mode - 0.0625f, 0.f), 0.875f);
        float bb = a + 0.125f;
        float4 p0, p1;
        p0.x = mode;
        p0.y = a;
        p0.z = bb;
        p0.w = (mode - a) * 8.f;
        p1.x = 1.f / (mode - a);
        p1.y = (bb - mode) * 8.f;
        p1.z = 1.f / (bb - mode);
        p1.w = 0.f;
        g_params4[((size_t)b * KA + tI) * 2 + 0] = p0;
        g_params4[((size_t)b * KA + tI) * 2 + 1] = p1;
    }
}

// =============================================================================
// K4: gamma_scaled + dense almat. 64-row tiles; warp-uniform k-quarter
// (P4 broadcast loads); streaming stores for the write-once almat.
// =============================================================================
__global__ __launch_bounds__(256)
void k4_out(float* __restrict__ out, int has_gamma)
{
    __shared__ float4 P4[KA * 2];
    __shared__ float gpart[256];
    __shared__ float gsm[64];
    int b = blockIdx.y, lt = blockIdx.x, tI = threadIdx.x;

    for (int i = tI; i < KA * 2; i += 256)
        P4[i] = g_params4[(size_t)b * KA * 2 + i];
    __syncthreads();

    int q = tI >> 6, row = tI & 63;
    int l = lt * 64 + row;
    float x = (float)l * (1.0f / 4095.0f);
    float g = 0.f;
    int ks = q * 64;
    int ke = (q == 3) ? KA : (ks + 64);
    for (int k = ks; k < ke; ++k) {
        float4 p0 = P4[k * 2], p1 = P4[k * 2 + 1];
        float mm = p0.x, a = p0.y, bb = p0.z, c1 = p0.w;
        float ima = p1.x, c2 = p1.y, ibm = p1.z;
        float u = fminf(fmaxf((x - a) * ima, 0.f), 1.f);
        float u2 = u * u, u4 = u2 * u2, u8 = u4 * u4;
        float left = c1 * (u8 * u8);
        float v = fminf(fmaxf((bb - x) * ibm, 0.f), 1.f);
        float v2 = v * v, v4 = v2 * v2, v8 = v4 * v4;
        float right = 1.f - c2 * (v8 * v8);
        g += (x <= mm) ? left : right;
    }
    gpart[tI] = g;
    __syncthreads();

    if (tI < 64) {
        float gv = ((gpart[tI] + gpart[64 + tI]) +
                    (gpart[128 + tI] + gpart[192 + tI]));
        gsm[tI] = gv;
        if (has_gamma) out[(size_t)b * LSEQ + lt * 64 + tI] = gv;
    }
    __syncthreads();

    float* almat = out + (has_gamma ? (size_t)BATCH * LSEQ : 0);
    int kq = tI & 63, rr = tI >> 6;
    float k0f = (float)(kq * 4);
    float* base = almat + ((size_t)b * LSEQ + (size_t)lt * 64) * KOUT + kq * 4;
    #pragma unroll 4
    for (int il = rr; il < 64; il += 4) {
        float gv = gsm[il];
        float4 v;
        v.x = fmaxf(1.f - fabsf(gv - k0f        ), 0.f);
        v.y = fmaxf(1.f - fabsf(gv - (k0f + 1.f)), 0.f);
        v.z = fmaxf(1.f - fabsf(gv - (k0f + 2.f)), 0.f);
        v.w = fmaxf(1.f - fabsf(gv - (k0f + 3.f)), 0.f);
        __stcs((float4*)(base + (size_t)il * KOUT), v);
    }
}

// =============================================================================
extern "C" void kernel_launch(void* const* d_in, const int* in_sizes, int n_in,
                              void* d_out, int out_size)
{
    const float* X    = (const float*)d_in[0];
    const float* mask = (const float*)d_in[1];
    const float* W1   = (const float*)d_in[2];
    const float* b1   = (const float*)d_in[3];
    const float* W2   = (const float*)d_in[4];
    const float* Wr   = (const float*)d_in[5];
    const float* br   = (const float*)d_in[6];
    float* out = (float*)d_out;

    cudaFuncSetAttribute(k1_attn, cudaFuncAttributeMaxDynamicSharedMemorySize,
                         SMEM_K1);

    k0_prep<<<96, 256>>>(W1, W2);
    k_dummy<<<1, 32>>>();            // position k1 at ncu capture index 3
    k_dummy<<<1, 32>>>();
    k1_attn<<<dim3(NCHUNK, BATCH), 256, SMEM_K1>>>(X, mask, b1, Wr);
    k23<<<BATCH, 256>>>(br);

    int has_gamma =
        ((size_t)out_size >= (size_t)BATCH * LSEQ * KOUT + (size_t)BATCH * LSEQ)
            ? 1 : 0;
    k4_out<<<dim3(LSEQ / 64, BATCH), 256>>>(out, has_gamma);
}

// round 14
// speedup vs baseline: 1.1384x; 1.1384x over previous
#include <cuda_runtime.h>
#include <cuda_fp16.h>
#include <math.h>
#include <stdint.h>

// Problem constants
#define BATCH   16
#define LSEQ    4096
#define DDIM    128
#define HDIM    256
#define KA      255
#define KOUT    256
#define LCHUNK  64
#define NCHUNK  64
#define MASKVAL -1e30f

// ---------------- device scratch (no allocation allowed) --------------------
__device__ float  g_partS0[BATCH * NCHUNK * 256];
__device__ float  g_partS1[BATCH * NCHUNK * 256];
__device__ float4 g_params4[BATCH * KA * 2];
// fp16 B-fragment images, PAIRED tiles (one LDS.128 = 2 tiles):
__device__ __align__(16) uint2 g_W1h[8192];     // 128 pairs x 64 = 64KB
__device__ __align__(16) uint2 g_W2h[16384];    // 256 pairs x 64 = 128KB

// ---------------- helpers ----------------------------------------------------
__device__ __forceinline__ uint32_t smem_u32(const void* p) {
    uint32_t a;
    asm("{ .reg .u64 t; cvta.to.shared.u64 t, %1; cvt.u32.u64 %0, t; }"
        : "=r"(a) : "l"(p));
    return a;
}
__device__ __forceinline__ void cp16(uint32_t dst, const void* src) {
    asm volatile("cp.async.cg.shared.global [%0], [%1], 16;"
                 :: "r"(dst), "l"(src) : "memory");
}
#define CP_COMMIT() asm volatile("cp.async.commit_group;" ::: "memory")
#define CP_WAIT0()  asm volatile("cp.async.wait_group 0;" ::: "memory")

__device__ __forceinline__ uint32_t hfpack(float a, float b) {
    __half ha = __float2half_rn(a);
    __half hb = __float2half_rn(b);
    return (uint32_t)__half_as_ushort(ha) |
           ((uint32_t)__half_as_ushort(hb) << 16);
}
__device__ __forceinline__ void mma_f16(float* c, const uint4& a,
                                        uint32_t b0, uint32_t b1) {
    asm volatile(
        "mma.sync.aligned.m16n8k16.row.col.f32.f16.f16.f32 "
        "{%0,%1,%2,%3}, {%4,%5,%6,%7}, {%8,%9}, {%0,%1,%2,%3};"
        : "+f"(c[0]), "+f"(c[1]), "+f"(c[2]), "+f"(c[3])
        : "r"(a.x), "r"(a.y), "r"(a.z), "r"(a.w), "r"(b0), "r"(b1));
}
__device__ __forceinline__ float ftanh(float x) {
    float e = __expf(2.f * x);
    return 1.f - __fdividef(2.f, e + 1.f);
}

// =============================================================================
// K0: fp16 B images with PAIRED tile layout: pair P at uint2 index
// P*64 + t*2 + half  ->  lane t's LDS.128 returns {tile 2P (xy), tile 2P+1 (zw)}.
// W1 pairs: kt*16 + p (p = ntG/2).  W2 pairs: c*64 + kt*4 + p (p within chunk).
// =============================================================================
__global__ void k0_prep(const float* __restrict__ W1, const float* __restrict__ W2)
{
    int g = blockIdx.x * 256 + threadIdx.x;
    if (g < 8192) {                 // W1 [128][256]
        int i1 = g >> 5, t = g & 31;
        int kt = i1 >> 5, ntG = i1 & 31;
        int n = ntG * 8 + (t >> 2);
        int k = kt * 16 + (t & 3) * 2;
        uint2 r;
        r.x = hfpack(W1[k * 256 + n],       W1[(k + 1) * 256 + n]);
        r.y = hfpack(W1[(k + 8) * 256 + n], W1[(k + 9) * 256 + n]);
        int p = ntG >> 1, half = ntG & 1;
        g_W1h[(kt * 16 + p) * 64 + t * 2 + half] = r;
    } else if (g < 8192 + 16384) {  // W2 [256][255] -> padded to 256 cols
        int g2 = g - 8192;
        int i2 = g2 >> 5, t = g2 & 31;
        int c = i2 >> 7, rem = i2 & 127;          // 64-col chunk c
        int kt = rem >> 3, nt = rem & 7;
        int n = c * 64 + nt * 8 + (t >> 2);
        int k = kt * 16 + (t & 3) * 2;
        float v0 = 0.f, v1 = 0.f, v2 = 0.f, v3 = 0.f;
        if (n < KA) {
            v0 = W2[k * KA + n];
            v1 = W2[(k + 1) * KA + n];
            v2 = W2[(k + 8) * KA + n];
            v3 = W2[(k + 9) * KA + n];
        }
        uint2 r;
        r.x = hfpack(v0, v1);
        r.y = hfpack(v2, v3);
        int p = nt >> 1, half = nt & 1;
        g_W2h[(c * 64 + kt * 4 + p) * 64 + t * 2 + half] = r;
    }
}

// dummy kernel: positions k1 at ncu's captured launch index (3)
__global__ void k_dummy() {}

// ---------------- K1 smem byte map (64-row chunk; ~105KB -> 2 blocks/SM) -----
// phase1: Xs single-term [0,16K), W1 B-frags [16K,80K)
// phase2: A2 single-term [0,32K) (aliases Xs), W2 double buffer 2x32KB [32K,96K)
#define X_OFF    0
#define W1_OFF   16384
#define A2_OFF   0
#define W2_OFF   32768
#define RS_B     98304
#define MS_B     98560
#define BS_B     98816
#define PART_B   99840
#define SMEM_K1  108032

// =============================================================================
// K1: 64-row L-chunks, 1024 blocks, 2 blocks/SM.
//   GEMM1: A=X fp16 single term (smem), B=W1 fp16 paired LDS.128.
//   GEMM2: A=T from smem per kt (NO register residency — R13's ah2[16]
//   register slice spilled to local mem, L2 11.5->22.5%); B=W2 paired LDS.128.
// =============================================================================
__global__ __launch_bounds__(256, 2)
void k1_attn(const float* __restrict__ X, const float* __restrict__ mask,
             const float* __restrict__ b1, const float* __restrict__ Wr)
{
    extern __shared__ char smc[];
    uint4*  Xs   = (uint4*)(smc + X_OFF);
    uint4*  W1s4 = (uint4*)(smc + W1_OFF);
    uint4*  A2s  = (uint4*)(smc + A2_OFF);
    float*  rsm  = (float*)(smc + RS_B);
    float*  msm  = (float*)(smc + MS_B);
    float*  bsm  = (float*)(smc + BS_B);
    float2* part = (float2*)(smc + PART_B);   // [4 warpM][256 cols]

    const uint32_t sb  = smem_u32(smc);
    const int tid = threadIdx.x;
    const int wid = tid >> 5;
    const int t   = tid & 31;
    const int b     = blockIdx.y;
    const int chunk = blockIdx.x;
    const int l0    = chunk * LCHUNK;

    const float* Xg = X + ((size_t)b * LSEQ + l0) * DDIM;

    // ---- issue W1 image copy (64KB) async; overlap with X staging ----
    {
        uint32_t dst = sb + W1_OFF;
        #pragma unroll
        for (int i = 0; i < 16; ++i)
            cp16(dst + (tid + i * 256) * 16, (const uint4*)g_W1h + tid + i * 256);
        CP_COMMIT();
    }

    // ---- stage X as single-term fp16 A-frags: 2 warps per m-tile ----
    {
        int mtile = wid >> 1;          // 4 m-tiles of 16 rows
        int khalf = wid & 1;
        int r0 = mtile * 16 + (t >> 2);
        const float* xr0 = Xg + r0 * DDIM;
        const float* xr1 = Xg + (r0 + 8) * DDIM;
        #pragma unroll
        for (int kq = 0; kq < 4; ++kq) {
            int kt = khalf * 4 + kq;
            int k0 = kt * 16 + (t & 3) * 2;
            float2 v00 = *(const float2*)(xr0 + k0);
            float2 v10 = *(const float2*)(xr1 + k0);
            float2 v01 = *(const float2*)(xr0 + k0 + 8);
            float2 v11 = *(const float2*)(xr1 + k0 + 8);
            uint4 hi;
            hi.x = hfpack(v00.x, v00.y);
            hi.y = hfpack(v10.x, v10.y);
            hi.z = hfpack(v01.x, v01.y);
            hi.w = hfpack(v11.x, v11.y);
            Xs[(mtile * 8 + kt) * 32 + t] = hi;
        }
    }

    // ---- small loads: rs = X.Wr, mask, b1 ----
    if (tid < 64) {
        float s0 = 0.f, s1 = 0.f, s2 = 0.f, s3 = 0.f;
        const float4* xr = (const float4*)(Xg + tid * DDIM);
        const float4* wr = (const float4*)Wr;
        #pragma unroll 8
        for (int d = 0; d < 32; ++d) {
            float4 xv = xr[d], wv = wr[d];
            s0 = fmaf(xv.x, wv.x, s0);
            s1 = fmaf(xv.y, wv.y, s1);
            s2 = fmaf(xv.z, wv.z, s2);
            s3 = fmaf(xv.w, wv.w, s3);
        }
        rsm[tid] = (s0 + s1) + (s2 + s3);
        msm[tid] = mask[(size_t)b * LSEQ + l0 + tid];
    }
    bsm[tid] = b1[tid];
    CP_WAIT0();
    __syncthreads();

    // GEMM1 layout: 2 m-groups of 2 m-tiles, 4 n-groups of 8 n-tiles (4 pairs)
    const int warpM1 = wid & 1;
    const int warpN1 = wid >> 1;

    // ---- GEMM1: acc[mt][nt][4] = X @ W1, paired-B LDS.128 ----
    float acc[2][8][4];
    #pragma unroll
    for (int mt = 0; mt < 2; ++mt)
        #pragma unroll
        for (int nt = 0; nt < 8; ++nt)
            #pragma unroll
            for (int q = 0; q < 4; ++q) acc[mt][nt][q] = 0.f;

    #pragma unroll 1
    for (int kt = 0; kt < 8; ++kt) {
        uint4 ah[2];
        #pragma unroll
        for (int mt = 0; mt < 2; ++mt) {
            int mtG = warpM1 * 2 + mt;
            ah[mt] = Xs[(mtG * 8 + kt) * 32 + t];
        }
        #pragma unroll
        for (int pp = 0; pp < 4; ++pp) {
            uint4 bb = W1s4[(kt * 16 + warpN1 * 4 + pp) * 32 + t];
            #pragma unroll
            for (int mt = 0; mt < 2; ++mt) {
                mma_f16(acc[mt][pp * 2 + 0], ah[mt], bb.x, bb.y);
                mma_f16(acc[mt][pp * 2 + 1], ah[mt], bb.z, bb.w);
            }
        }
    }
    __syncthreads();   // all warps done reading X/W1

    // ---- prefetch W2 chunk 0 (32KB) into buf0; overlaps tanh epilogue ----
    {
        uint32_t dst = sb + W2_OFF;
        #pragma unroll
        for (int i = 0; i < 8; ++i)
            cp16(dst + (tid + i * 256) * 16, (const uint4*)g_W2h + tid + i * 256);
        CP_COMMIT();
    }

    // ---- epilogue 1: T = tanh(acc + b1) -> single fp16 term -> A2 frags ----
    #pragma unroll
    for (int mt = 0; mt < 2; ++mt) {
        int mtG = warpM1 * 2 + mt;
        #pragma unroll
        for (int j = 0; j < 4; ++j) {
            int nt0 = 2 * j, nt1 = 2 * j + 1;
            int c0 = (warpN1 * 8 + nt0) * 8 + (t & 3) * 2;
            int c1 = (warpN1 * 8 + nt1) * 8 + (t & 3) * 2;
            float b00 = bsm[c0], b01 = bsm[c0 + 1];
            float b10 = bsm[c1], b11 = bsm[c1 + 1];
            uint4 hi;
            hi.x = hfpack(ftanh(acc[mt][nt0][0] + b00), ftanh(acc[mt][nt0][1] + b01));
            hi.y = hfpack(ftanh(acc[mt][nt0][2] + b00), ftanh(acc[mt][nt0][3] + b01));
            hi.z = hfpack(ftanh(acc[mt][nt1][0] + b10), ftanh(acc[mt][nt1][1] + b11));
            hi.w = hfpack(ftanh(acc[mt][nt1][2] + b10), ftanh(acc[mt][nt1][3] + b11));
            int ktG = warpN1 * 4 + j;
            A2s[(mtG * 16 + ktG) * 32 + t] = hi;
        }
    }

    // GEMM2 layout: 4 m-groups of 1 m-tile, 2 n-groups of 4 n-tiles (2 pairs)
    const int warpM = wid & 3;     // mtG
    const int warpN = wid >> 2;    // 0..1

    const float mv0 = msm[warpM * 16 + (t >> 2)];
    const float mv1 = msm[warpM * 16 + (t >> 2) + 8];
    const float rw0 = rsm[warpM * 16 + (t >> 2)];
    const float rw1 = rsm[warpM * 16 + (t >> 2) + 8];

    #pragma unroll 1
    for (int c = 0; c < 4; ++c) {
        CP_WAIT0();
        __syncthreads();   // buf[c&1] staged; A2 visible (c==0); prev reads done

        // prefetch chunk c+1 into the other buffer (hidden under mma below)
        if (c < 3) {
            uint32_t dst = sb + W2_OFF + ((c + 1) & 1) * 32768;
            const uint4* src = (const uint4*)g_W2h + (c + 1) * 2048;
            #pragma unroll
            for (int i = 0; i < 8; ++i)
                cp16(dst + (tid + i * 256) * 16, src + tid + i * 256);
            CP_COMMIT();
        }

        const uint4* W2s4 = (const uint4*)(smc + W2_OFF + (c & 1) * 32768);

        float acc2[4][4];
        #pragma unroll
        for (int nt = 0; nt < 4; ++nt)
            #pragma unroll
            for (int q = 0; q < 4; ++q) acc2[nt][q] = 0.f;

        #pragma unroll 4
        for (int kt = 0; kt < 16; ++kt) {
            uint4 ah = A2s[(warpM * 16 + kt) * 32 + t];
            #pragma unroll
            for (int ntp = 0; ntp < 2; ++ntp) {
                uint4 bb = W2s4[(kt * 4 + warpN * 2 + ntp) * 32 + t];
                mma_f16(acc2[ntp * 2 + 0], ah, bb.x, bb.y);
                mma_f16(acc2[ntp * 2 + 1], ah, bb.z, bb.w);
            }
        }

        // per-chunk epilogue: e = exp(masked logit); column sums over 16 rows
        #pragma unroll
        for (int nt = 0; nt < 4; ++nt) {
            float e0 = __expf(mv0 * acc2[nt][0] + (1.f - mv0) * MASKVAL);
            float e1 = __expf(mv0 * acc2[nt][1] + (1.f - mv0) * MASKVAL);
            float e2 = __expf(mv1 * acc2[nt][2] + (1.f - mv1) * MASKVAL);
            float e3 = __expf(mv1 * acc2[nt][3] + (1.f - mv1) * MASKVAL);
            float s0A = e0 + e2;
            float s0B = e1 + e3;
            float s1A = fmaf(e0, rw0, e2 * rw1);
            float s1B = fmaf(e1, rw0, e3 * rw1);
            #pragma unroll
            for (int o = 4; o < 32; o <<= 1) {
                s0A += __shfl_xor_sync(0xffffffffu, s0A, o);
                s0B += __shfl_xor_sync(0xffffffffu, s0B, o);
                s1A += __shfl_xor_sync(0xffffffffu, s1A, o);
                s1B += __shfl_xor_sync(0xffffffffu, s1B, o);
            }
            if (t < 4) {
                int col = c * 64 + (warpN * 4 + nt) * 8 + t * 2;
                part[warpM * 256 + col]     = make_float2(s0A, s1A);
                part[warpM * 256 + col + 1] = make_float2(s0B, s1B);
            }
        }
    }
    __syncthreads();

    // ---- final cross-warp column reduce -> global partials ----
    {
        float2 p0 = part[tid];
        float2 p1 = part[256 + tid];
        float2 p2 = part[512 + tid];
        float2 p3 = part[768 + tid];
        size_t idx = ((size_t)b * NCHUNK + chunk) * 256 + tid;
        g_partS0[idx] = (p0.x + p1.x) + (p2.x + p3.x);
        g_partS1[idx] = (p0.y + p1.y) + (p2.y + p3.y);
    }
}

// =============================================================================
// K23: per batch: reduce chunk partials -> mu; softmax+cumsum -> cdf params
// =============================================================================
__global__ void k23(const float* __restrict__ br)
{
    __shared__ float sm_mu[256];
    __shared__ float ws[8];
    __shared__ float bc[2];
    int b = blockIdx.x, tI = threadIdx.x;
    int lane = tI & 31, warp = tI >> 5;

    float s0 = 0.f, s1 = 0.f;
    #pragma unroll 4
    for (int c = 0; c < NCHUNK; ++c) {
        size_t idx = ((size_t)b * NCHUNK + c) * 256 + tI;
        s0 += g_partS0[idx];
        s1 += g_partS1[idx];
    }
    sm_mu[tI] = s1 / s0 + br[0];
    __syncthreads();

    float e = (tI == 0) ? 0.f : sm_mu[tI - 1];

    float m = e;
    #pragma unroll
    for (int o = 16; o; o >>= 1) m = fmaxf(m, __shfl_xor_sync(0xffffffffu, m, o));
    if (lane == 0) ws[warp] = m;
    __syncthreads();
    if (tI < 8) {
        float v = ws[tI];
        #pragma unroll
        for (int o = 4; o; o >>= 1) v = fmaxf(v, __shfl_xor_sync(0xffu, v, o));
        if (tI == 0) bc[0] = v;
    }
    __syncthreads();
    float M = bc[0];

    float p = expf(e - M);
    float s = p;
    #pragma unroll
    for (int o = 16; o; o >>= 1) s += __shfl_xor_sync(0xffffffffu, s, o);
    if (lane == 0) ws[warp] = s;
    __syncthreads();
    if (tI < 8) {
        float v = ws[tI];
        #pragma unroll
        for (int o = 4; o; o >>= 1) v += __shfl_xor_sync(0xffu, v, o);
        if (tI == 0) bc[1] = v;
    }
    __syncthreads();
    p /= bc[1];

    float v = p;
    #pragma unroll
    for (int o = 1; o < 32; o <<= 1) {
        float u = __shfl_up_sync(0xffffffffu, v, o);
        if (lane >= o) v += u;
    }
    if (lane == 31) ws[warp] = v;
    __syncthreads();
    if (warp == 0 && lane < 8) {
        float w = ws[lane];
        #pragma unroll
        for (int o = 1; o < 8; o <<= 1) {
            float u = __shfl_up_sync(0xffu, w, o);
            if (lane >= o) w += u;
        }
        ws[lane] = w;
    }
    __syncthreads();
    float cum = v + (warp ? ws[warp - 1] : 0.f);

    if (tI < KA) {
        float mode = fminf(fmaxf(cum, 1e-4f), 0.9999f);
        float a  = fminf(fmaxf(mode - 0.0625f, 0.f), 0.875f);
        float bb = a + 0.125f;
        float4 p0, p1;
        p0.x = mode;
        p0.y = a;
        p0.z = bb;
        p0.w = (mode - a) * 8.f;
        p1.x = 1.f / (mode - a);
        p1.y = (bb - mode) * 8.f;
        p1.z = 1.f / (bb - mode);
        p1.w = 0.f;
        g_params4[((size_t)b * KA + tI) * 2 + 0] = p0;
        g_params4[((size_t)b * KA + tI) * 2 + 1] = p1;
    }
}

// =============================================================================
// K4: gamma_scaled + dense almat. 64-row tiles; warp-uniform k-quarter
// (P4 broadcast loads); streaming stores for the write-once almat.
// =============================================================================
__global__ __launch_bounds__(256)
void k4_out(float* __restrict__ out, int has_gamma)
{
    __shared__ float4 P4[KA * 2];
    __shared__ float gpart[256];
    __shared__ float gsm[64];
    int b = blockIdx.y, lt = blockIdx.x, tI = threadIdx.x;

    for (int i = tI; i < KA * 2; i += 256)
        P4[i] = g_params4[(size_t)b * KA * 2 + i];
    __syncthreads();

    int q = tI >> 6, row = tI & 63;
    int l = lt * 64 + row;
    float x = (float)l * (1.0f / 4095.0f);
    float g = 0.f;
    int ks = q * 64;
    int ke = (q == 3) ? KA : (ks + 64);
    for (int k = ks; k < ke; ++k) {
        float4 p0 = P4[k * 2], p1 = P4[k * 2 + 1];
        float mm = p0.x, a = p0.y, bb = p0.z, c1 = p0.w;
        float ima = p1.x, c2 = p1.y, ibm = p1.z;
        float u = fminf(fmaxf((x - a) * ima, 0.f), 1.f);
        float u2 = u * u, u4 = u2 * u2, u8 = u4 * u4;
        float left = c1 * (u8 * u8);
        float v = fminf(fmaxf((bb - x) * ibm, 0.f), 1.f);
        float v2 = v * v, v4 = v2 * v2, v8 = v4 * v4;
        float right = 1.f - c2 * (v8 * v8);
        g += (x <= mm) ? left : right;
    }
    gpart[tI] = g;
    __syncthreads();

    if (tI < 64) {
        float gv = ((gpart[tI] + gpart[64 + tI]) +
                    (gpart[128 + tI] + gpart[192 + tI]));
        gsm[tI] = gv;
        if (has_gamma) out[(size_t)b * LSEQ + lt * 64 + tI] = gv;
    }
    __syncthreads();

    float* almat = out + (has_gamma ? (size_t)BATCH * LSEQ : 0);
    int kq = tI & 63, rr = tI >> 6;
    float k0f = (float)(kq * 4);
    float* base = almat + ((size_t)b * LSEQ + (size_t)lt * 64) * KOUT + kq * 4;
    #pragma unroll 4
    for (int il = rr; il < 64; il += 4) {
        float gv = gsm[il];
        float4 v;
        v.x = fmaxf(1.f - fabsf(gv - k0f        ), 0.f);
        v.y = fmaxf(1.f - fabsf(gv - (k0f + 1.f)), 0.f);
        v.z = fmaxf(1.f - fabsf(gv - (k0f + 2.f)), 0.f);
        v.w = fmaxf(1.f - fabsf(gv - (k0f + 3.f)), 0.f);
        __stcs((float4*)(base + (size_t)il * KOUT), v);
    }
}

// =============================================================================
extern "C" void kernel_launch(void* const* d_in, const int* in_sizes, int n_in,
                              void* d_out, int out_size)
{
    const float* X    = (const float*)d_in[0];
    const float* mask = (const float*)d_in[1];
    const float* W1   = (const float*)d_in[2];
    const float* b1   = (const float*)d_in[3];
    const float* W2   = (const float*)d_in[4];
    const float* Wr   = (const float*)d_in[5];
    const float* br   = (const float*)d_in[6];
    float* out = (float*)d_out;

    cudaFuncSetAttribute(k1_attn, cudaFuncAttributeMaxDynamicSharedMemorySize,
                         SMEM_K1);

    k0_prep<<<96, 256>>>(W1, W2);
    k_dummy<<<1, 32>>>();            // position k1 at ncu capture index 3
    k_dummy<<<1, 32>>>();
    k1_attn<<<dim3(NCHUNK, BATCH), 256, SMEM_K1>>>(X, mask, b1, Wr);
    k23<<<BATCH, 256>>>(br);

    int has_gamma =
        ((size_t)out_size >= (size_t)BATCH * LSEQ * KOUT + (size_t)BATCH * LSEQ)
            ? 1 : 0;
    k4_out<<<dim3(LSEQ / 64, BATCH), 256>>>(out, has_gamma);
}

// round 15
// speedup vs baseline: 1.2345x; 1.0844x over previous
#include <cuda_runtime.h>
#include <cuda_fp16.h>
#include <math.h>
#include <stdint.h>

// Problem constants
#define BATCH   16
#define LSEQ    4096
#define DDIM    128
#define HDIM    256
#define KA      255
#define KOUT    256
#define LCHUNK  64
#define NCHUNK  64
#define MASKVAL -1e30f

// ---------------- device scratch (no allocation allowed) --------------------
__device__ float  g_partS0[BATCH * NCHUNK * 256];
__device__ float  g_partS1[BATCH * NCHUNK * 256];
__device__ float4 g_params4[BATCH * KA * 2];
// fp16 B-fragment images, PAIRED tiles (one LDS.128 = 2 tiles):
__device__ __align__(16) uint2 g_W1h[8192];     // 128 pairs x 64 = 64KB
__device__ __align__(16) uint2 g_W2h[16384];    // 256 pairs x 64 = 128KB

// ---------------- helpers ----------------------------------------------------
__device__ __forceinline__ uint32_t smem_u32(const void* p) {
    uint32_t a;
    asm("{ .reg .u64 t; cvta.to.shared.u64 t, %1; cvt.u32.u64 %0, t; }"
        : "=r"(a) : "l"(p));
    return a;
}
__device__ __forceinline__ void cp16(uint32_t dst, const void* src) {
    asm volatile("cp.async.cg.shared.global [%0], [%1], 16;"
                 :: "r"(dst), "l"(src) : "memory");
}
#define CP_COMMIT() asm volatile("cp.async.commit_group;" ::: "memory")
#define CP_WAIT0()  asm volatile("cp.async.wait_group 0;" ::: "memory")

__device__ __forceinline__ uint32_t hfpack(float a, float b) {
    __half ha = __float2half_rn(a);
    __half hb = __float2half_rn(b);
    return (uint32_t)__half_as_ushort(ha) |
           ((uint32_t)__half_as_ushort(hb) << 16);
}
__device__ __forceinline__ void mma_f16(float* c, const uint4& a,
                                        uint32_t b0, uint32_t b1) {
    asm volatile(
        "mma.sync.aligned.m16n8k16.row.col.f32.f16.f16.f32 "
        "{%0,%1,%2,%3}, {%4,%5,%6,%7}, {%8,%9}, {%0,%1,%2,%3};"
        : "+f"(c[0]), "+f"(c[1]), "+f"(c[2]), "+f"(c[3])
        : "r"(a.x), "r"(a.y), "r"(a.z), "r"(a.w), "r"(b0), "r"(b1));
}
__device__ __forceinline__ float ftanh(float x) {
    float e = __expf(2.f * x);
    return 1.f - __fdividef(2.f, e + 1.f);
}

// =============================================================================
// K0: fp16 B images, PAIRED tile layout (lane t LDS.128 = tiles {2P, 2P+1}).
// W1 pairs: kt*16 + p.  W2 pairs ordered for 128-col chunks:
//   c (n>>7), kt (k>>4), p (pair within chunk) -> index (c*128 + kt*8 + p).
// =============================================================================
__global__ void k0_prep(const float* __restrict__ W1, const float* __restrict__ W2)
{
    int g = blockIdx.x * 256 + threadIdx.x;
    if (g < 8192) {                 // W1 [128][256]
        int i1 = g >> 5, t = g & 31;
        int kt = i1 >> 5, ntG = i1 & 31;
        int n = ntG * 8 + (t >> 2);
        int k = kt * 16 + (t & 3) * 2;
        uint2 r;
        r.x = hfpack(W1[k * 256 + n],       W1[(k + 1) * 256 + n]);
        r.y = hfpack(W1[(k + 8) * 256 + n], W1[(k + 9) * 256 + n]);
        int p = ntG >> 1, half = ntG & 1;
        g_W1h[(kt * 16 + p) * 64 + t * 2 + half] = r;
    } else if (g < 8192 + 16384) {  // W2 [256][255] -> padded to 256 cols
        int g2 = g - 8192;
        int i2 = g2 >> 5, t = g2 & 31;
        int c = i2 >> 7, rem = i2 & 127;          // 128-col chunk c, tile rem
        int kt = rem >> 3, nt = rem & 7;          // rem scans 16 nt per kt? no:
        // rem = kt*8 + ntp is wrong for 16 nt; use: nt index within chunk 0..15
        // Re-derive: i2 enumerates (c, ktn) with ktn in [0,128): kt = ktn>>3 is
        // only 8 nt. Need 16 nt per kt -> use two g-passes per (c,kt): handled
        // by mapping ktn = kt*8 + p where p is the PAIR index (8 pairs = 16 nt)
        // and t covers both halves via the half bit below? No: each pair needs
        // 64 uint2 writes (2 halves x 32 lanes) = 2 tiles. i2 covers 32 writes.
        // So enumerate tiles directly: tile = c*256 + kt*16 + nt (nt in [0,16)).
        // i2 in [0,512) = 2 chunks * 16 kt * 16 nt.
        int tile = i2;
        int cc = tile >> 8, r2 = tile & 255;
        int kt2 = r2 >> 4, nt2 = r2 & 15;
        int n = cc * 128 + nt2 * 8 + (t >> 2);
        int k = kt2 * 16 + (t & 3) * 2;
        float v0 = 0.f, v1 = 0.f, v2 = 0.f, v3 = 0.f;
        if (n < KA) {
            v0 = W2[k * KA + n];
            v1 = W2[(k + 1) * KA + n];
            v2 = W2[(k + 8) * KA + n];
            v3 = W2[(k + 9) * KA + n];
        }
        uint2 r;
        r.x = hfpack(v0, v1);
        r.y = hfpack(v2, v3);
        int p = nt2 >> 1, half = nt2 & 1;
        g_W2h[(cc * 128 + kt2 * 8 + p) * 64 + t * 2 + half] = r;
    }
}

// ---------------- K1 smem byte map (64-row chunk; ~102KB -> 2 blocks/SM) -----
// phase1: Xs [0,16K), W1 B-frags [16K,80K)
// phase2: A2 [0,32K) (aliases Xs+W1 head), W2 single 64KB buffer [32K,96K)
#define X_OFF    0
#define W1_OFF   16384
#define A2_OFF   0
#define W2_OFF   32768
#define RS_B     98304
#define MS_B     98560
#define BS_B     98816
#define PART_B   99840
#define SMEM_K1  104448

// =============================================================================
// K1: 64-row L-chunks, 1024 blocks, 2 blocks/SM.
//   GEMM1: A=X fp16 (smem), B=W1 paired LDS.128, gM=2 x gN=4.
//   GEMM2: TWO 128-col chunks, single 64KB buffer, gM=2 (2 m-tiles/warp) x
//   gN=4 — crossbar bytes 768KB -> 512KB/block (A x4 + B x2 per chunk).
// =============================================================================
__global__ __launch_bounds__(256, 2)
void k1_attn(const float* __restrict__ X, const float* __restrict__ mask,
             const float* __restrict__ b1, const float* __restrict__ Wr)
{
    extern __shared__ char smc[];
    uint4*  Xs   = (uint4*)(smc + X_OFF);
    uint4*  W1s4 = (uint4*)(smc + W1_OFF);
    uint4*  A2s  = (uint4*)(smc + A2_OFF);
    uint4*  W2s4 = (uint4*)(smc + W2_OFF);
    float*  rsm  = (float*)(smc + RS_B);
    float*  msm  = (float*)(smc + MS_B);
    float*  bsm  = (float*)(smc + BS_B);
    float2* part = (float2*)(smc + PART_B);   // [2 warpM][256 cols]

    const uint32_t sb  = smem_u32(smc);
    const int tid = threadIdx.x;
    const int wid = tid >> 5;
    const int t   = tid & 31;
    const int b     = blockIdx.y;
    const int chunk = blockIdx.x;
    const int l0    = chunk * LCHUNK;

    const float* Xg = X + ((size_t)b * LSEQ + l0) * DDIM;

    // ---- issue W1 image copy (64KB) async; overlap with X staging ----
    {
        uint32_t dst = sb + W1_OFF;
        #pragma unroll
        for (int i = 0; i < 16; ++i)
            cp16(dst + (tid + i * 256) * 16, (const uint4*)g_W1h + tid + i * 256);
        CP_COMMIT();
    }

    // ---- stage X as single-term fp16 A-frags: 2 warps per m-tile ----
    {
        int mtile = wid >> 1;          // 4 m-tiles of 16 rows
        int khalf = wid & 1;
        int r0 = mtile * 16 + (t >> 2);
        const float* xr0 = Xg + r0 * DDIM;
        const float* xr1 = Xg + (r0 + 8) * DDIM;
        #pragma unroll
        for (int kq = 0; kq < 4; ++kq) {
            int kt = khalf * 4 + kq;
            int k0 = kt * 16 + (t & 3) * 2;
            float2 v00 = *(const float2*)(xr0 + k0);
            float2 v10 = *(const float2*)(xr1 + k0);
            float2 v01 = *(const float2*)(xr0 + k0 + 8);
            float2 v11 = *(const float2*)(xr1 + k0 + 8);
            uint4 hi;
            hi.x = hfpack(v00.x, v00.y);
            hi.y = hfpack(v10.x, v10.y);
            hi.z = hfpack(v01.x, v01.y);
            hi.w = hfpack(v11.x, v11.y);
            Xs[(mtile * 8 + kt) * 32 + t] = hi;
        }
    }

    // ---- small loads: rs = X.Wr, mask, b1 ----
    if (tid < 64) {
        float s0 = 0.f, s1 = 0.f, s2 = 0.f, s3 = 0.f;
        const float4* xr = (const float4*)(Xg + tid * DDIM);
        const float4* wr = (const float4*)Wr;
        #pragma unroll 8
        for (int d = 0; d < 32; ++d) {
            float4 xv = xr[d], wv = wr[d];
            s0 = fmaf(xv.x, wv.x, s0);
            s1 = fmaf(xv.y, wv.y, s1);
            s2 = fmaf(xv.z, wv.z, s2);
            s3 = fmaf(xv.w, wv.w, s3);
        }
        rsm[tid] = (s0 + s1) + (s2 + s3);
        msm[tid] = mask[(size_t)b * LSEQ + l0 + tid];
    }
    bsm[tid] = b1[tid];
    CP_WAIT0();
    __syncthreads();

    // GEMM1 layout: 2 m-groups of 2 m-tiles, 4 n-groups of 8 n-tiles (4 pairs)
    const int warpM1 = wid & 1;
    const int warpN1 = wid >> 1;

    float acc[2][8][4];
    #pragma unroll
    for (int mt = 0; mt < 2; ++mt)
        #pragma unroll
        for (int nt = 0; nt < 8; ++nt)
            #pragma unroll
            for (int q = 0; q < 4; ++q) acc[mt][nt][q] = 0.f;

    #pragma unroll 1
    for (int kt = 0; kt < 8; ++kt) {
        uint4 ah[2];
        #pragma unroll
        for (int mt = 0; mt < 2; ++mt) {
            int mtG = warpM1 * 2 + mt;
            ah[mt] = Xs[(mtG * 8 + kt) * 32 + t];
        }
        #pragma unroll
        for (int pp = 0; pp < 4; ++pp) {
            uint4 bb = W1s4[(kt * 16 + warpN1 * 4 + pp) * 32 + t];
            #pragma unroll
            for (int mt = 0; mt < 2; ++mt) {
                mma_f16(acc[mt][pp * 2 + 0], ah[mt], bb.x, bb.y);
                mma_f16(acc[mt][pp * 2 + 1], ah[mt], bb.z, bb.w);
            }
        }
    }
    __syncthreads();   // all warps done reading Xs/W1

    // ---- stage W2 chunk 0 (64KB) into the single buffer; overlaps epi-1 ----
    {
        uint32_t dst = sb + W2_OFF;
        #pragma unroll
        for (int i = 0; i < 16; ++i)
            cp16(dst + (tid + i * 256) * 16, (const uint4*)g_W2h + tid + i * 256);
        CP_COMMIT();
    }

    // ---- epilogue 1: T = tanh(acc + b1) -> fp16 -> A2 frags ----
    #pragma unroll
    for (int mt = 0; mt < 2; ++mt) {
        int mtG = warpM1 * 2 + mt;
        #pragma unroll
        for (int j = 0; j < 4; ++j) {
            int nt0 = 2 * j, nt1 = 2 * j + 1;
            int c0 = (warpN1 * 8 + nt0) * 8 + (t & 3) * 2;
            int c1 = (warpN1 * 8 + nt1) * 8 + (t & 3) * 2;
            float b00 = bsm[c0], b01 = bsm[c0 + 1];
            float b10 = bsm[c1], b11 = bsm[c1 + 1];
            uint4 hi;
            hi.x = hfpack(ftanh(acc[mt][nt0][0] + b00), ftanh(acc[mt][nt0][1] + b01));
            hi.y = hfpack(ftanh(acc[mt][nt0][2] + b00), ftanh(acc[mt][nt0][3] + b01));
            hi.z = hfpack(ftanh(acc[mt][nt1][0] + b10), ftanh(acc[mt][nt1][1] + b11));
            hi.w = hfpack(ftanh(acc[mt][nt1][2] + b10), ftanh(acc[mt][nt1][3] + b11));
            int ktG = warpN1 * 4 + j;
            A2s[(mtG * 16 + ktG) * 32 + t] = hi;
        }
    }

    // GEMM2: gM=2 (2 m-tiles each), gN=4 (32 cols each), 2 chunks of 128 cols
    const int warpM = wid & 1;
    const int warpN = wid >> 1;

    float mva[2], mvb[2], rwa[2], rwb[2];
    #pragma unroll
    for (int mt = 0; mt < 2; ++mt) {
        int row = warpM * 32 + mt * 16 + (t >> 2);
        mva[mt] = msm[row];     mvb[mt] = msm[row + 8];
        rwa[mt] = rsm[row];     rwb[mt] = rsm[row + 8];
    }

    CP_WAIT0();
    __syncthreads();   // chunk-0 W2 staged AND A2 writes visible

    #pragma unroll 1
    for (int c = 0; c < 2; ++c) {
        if (c == 1) {
            __syncthreads();   // all warps done reading chunk-0 buffer
            uint32_t dst = sb + W2_OFF;
            #pragma unroll
            for (int i = 0; i < 16; ++i)
                cp16(dst + (tid + i * 256) * 16,
                     (const uint4*)g_W2h + 4096 + tid + i * 256);
            CP_COMMIT();
            CP_WAIT0();
            __syncthreads();   // chunk-1 staged, visible to all
        }

        float acc2[2][4][4];
        #pragma unroll
        for (int mt = 0; mt < 2; ++mt)
            #pragma unroll
            for (int nt = 0; nt < 4; ++nt)
                #pragma unroll
                for (int q = 0; q < 4; ++q) acc2[mt][nt][q] = 0.f;

        #pragma unroll 4
        for (int kt = 0; kt < 16; ++kt) {
            uint4 ah[2];
            #pragma unroll
            for (int mt = 0; mt < 2; ++mt)
                ah[mt] = A2s[((warpM * 2 + mt) * 16 + kt) * 32 + t];
            #pragma unroll
            for (int pp = 0; pp < 2; ++pp) {
                uint4 bb = W2s4[(kt * 8 + warpN * 2 + pp) * 32 + t];
                #pragma unroll
                for (int mt = 0; mt < 2; ++mt) {
                    mma_f16(acc2[mt][pp * 2 + 0], ah[mt], bb.x, bb.y);
                    mma_f16(acc2[mt][pp * 2 + 1], ah[mt], bb.z, bb.w);
                }
            }
        }

        // epilogue: e = exp(masked logit); column sums over this warp's 32 rows
        #pragma unroll
        for (int nt = 0; nt < 4; ++nt) {
            float s0A = 0.f, s0B = 0.f, s1A = 0.f, s1B = 0.f;
            #pragma unroll
            for (int mt = 0; mt < 2; ++mt) {
                float e0 = __expf(mva[mt] * acc2[mt][nt][0] + (1.f - mva[mt]) * MASKVAL);
                float e1 = __expf(mva[mt] * acc2[mt][nt][1] + (1.f - mva[mt]) * MASKVAL);
                float e2 = __expf(mvb[mt] * acc2[mt][nt][2] + (1.f - mvb[mt]) * MASKVAL);
                float e3 = __expf(mvb[mt] * acc2[mt][nt][3] + (1.f - mvb[mt]) * MASKVAL);
                s0A += e0 + e2;
                s0B += e1 + e3;
                s1A += fmaf(e0, rwa[mt], e2 * rwb[mt]);
                s1B += fmaf(e1, rwa[mt], e3 * rwb[mt]);
            }
            #pragma unroll
            for (int o = 4; o < 32; o <<= 1) {
                s0A += __shfl_xor_sync(0xffffffffu, s0A, o);
                s0B += __shfl_xor_sync(0xffffffffu, s0B, o);
                s1A += __shfl_xor_sync(0xffffffffu, s1A, o);
                s1B += __shfl_xor_sync(0xffffffffu, s1B, o);
            }
            if (t < 4) {
                int col = c * 128 + warpN * 32 + nt * 8 + t * 2;
                part[warpM * 256 + col]     = make_float2(s0A, s1A);
                part[warpM * 256 + col + 1] = make_float2(s0B, s1B);
            }
        }
    }
    __syncthreads();

    // ---- final cross-warp column reduce -> global partials ----
    {
        float2 p0 = part[tid];
        float2 p1 = part[256 + tid];
        size_t idx = ((size_t)b * NCHUNK + chunk) * 256 + tid;
        g_partS0[idx] = p0.x + p1.x;
        g_partS1[idx] = p0.y + p1.y;
    }
}

// =============================================================================
// K23: per batch: reduce chunk partials -> mu; softmax+cumsum -> cdf params
// =============================================================================
__global__ void k23(const float* __restrict__ br)
{
    __shared__ float sm_mu[256];
    __shared__ float ws[8];
    __shared__ float bc[2];
    int b = blockIdx.x, tI = threadIdx.x;
    int lane = tI & 31, warp = tI >> 5;

    float s0 = 0.f, s1 = 0.f;
    #pragma unroll 4
    for (int c = 0; c < NCHUNK; ++c) {
        size_t idx = ((size_t)b * NCHUNK + c) * 256 + tI;
        s0 += g_partS0[idx];
        s1 += g_partS1[idx];
    }
    sm_mu[tI] = s1 / s0 + br[0];
    __syncthreads();

    float e = (tI == 0) ? 0.f : sm_mu[tI - 1];

    float m = e;
    #pragma unroll
    for (int o = 16; o; o >>= 1) m = fmaxf(m, __shfl_xor_sync(0xffffffffu, m, o));
    if (lane == 0) ws[warp] = m;
    __syncthreads();
    if (tI < 8) {
        float v = ws[tI];
        #pragma unroll
        for (int o = 4; o; o >>= 1) v = fmaxf(v, __shfl_xor_sync(0xffu, v, o));
        if (tI == 0) bc[0] = v;
    }
    __syncthreads();
    float M = bc[0];

    float p = expf(e - M);
    float s = p;
    #pragma unroll
    for (int o = 16; o; o >>= 1) s += __shfl_xor_sync(0xffffffffu, s, o);
    if (lane == 0) ws[warp] = s;
    __syncthreads();
    if (tI < 8) {
        float v = ws[tI];
        #pragma unroll
        for (int o = 4; o; o >>= 1) v += __shfl_xor_sync(0xffu, v, o);
        if (tI == 0) bc[1] = v;
    }
    __syncthreads();
    p /= bc[1];

    float v = p;
    #pragma unroll
    for (int o = 1; o < 32; o <<= 1) {
        float u = __shfl_up_sync(0xffffffffu, v, o);
        if (lane >= o) v += u;
    }
    if (lane == 31) ws[warp] = v;
    __syncthreads();
    if (warp == 0 && lane < 8) {
        float w = ws[lane];
        #pragma unroll
        for (int o = 1; o < 8; o <<= 1) {
            float u = __shfl_up_sync(0xffu, w, o);
            if (lane >= o) w += u;
        }
        ws[lane] = w;
    }
    __syncthreads();
    float cum = v + (warp ? ws[warp - 1] : 0.f);

    if (tI < KA) {
        float mode = fminf(fmaxf(cum, 1e-4f), 0.9999f);
        float a  = fminf(fmaxf(mode - 0.0625f, 0.f), 0.875f);
        float bb = a + 0.125f;
        float4 p0, p1;
        p0.x = mode;
        p0.y = a;
        p0.z = bb;
        p0.w = (mode - a) * 8.f;
        p1.x = 1.f / (mode - a);
        p1.y = (bb - mode) * 8.f;
        p1.z = 1.f / (bb - mode);
        p1.w = 0.f;
        g_params4[((size_t)b * KA + tI) * 2 + 0] = p0;
        g_params4[((size_t)b * KA + tI) * 2 + 1] = p1;
    }
}

// =============================================================================
// K4: gamma_scaled + dense almat. 64-row tiles; warp-uniform k-quarter
// (P4 broadcast loads); streaming stores for the write-once almat.
// =============================================================================
__global__ __launch_bounds__(256)
void k4_out(float* __restrict__ out, int has_gamma)
{
    __shared__ float4 P4[KA * 2];
    __shared__ float gpart[256];
    __shared__ float gsm[64];
    int b = blockIdx.y, lt = blockIdx.x, tI = threadIdx.x;

    for (int i = tI; i < KA * 2; i += 256)
        P4[i] = g_params4[(size_t)b * KA * 2 + i];
    __syncthreads();

    int q = tI >> 6, row = tI & 63;
    int l = lt * 64 + row;
    float x = (float)l * (1.0f / 4095.0f);
    float g = 0.f;
    int ks = q * 64;
    int ke = (q == 3) ? KA : (ks + 64);
    for (int k = ks; k < ke; ++k) {
        float4 p0 = P4[k * 2], p1 = P4[k * 2 + 1];
        float mm = p0.x, a = p0.y, bb = p0.z, c1 = p0.w;
        float ima = p1.x, c2 = p1.y, ibm = p1.z;
        float u = fminf(fmaxf((x - a) * ima, 0.f), 1.f);
        float u2 = u * u, u4 = u2 * u2, u8 = u4 * u4;
        float left = c1 * (u8 * u8);
        float v = fminf(fmaxf((bb - x) * ibm, 0.f), 1.f);
        float v2 = v * v, v4 = v2 * v2, v8 = v4 * v4;
        float right = 1.f - c2 * (v8 * v8);
        g += (x <= mm) ? left : right;
    }
    gpart[tI] = g;
    __syncthreads();

    if (tI < 64) {
        float gv = ((gpart[tI] + gpart[64 + tI]) +
                    (gpart[128 + tI] + gpart[192 + tI]));
        gsm[tI] = gv;
        if (has_gamma) out[(size_t)b * LSEQ + lt * 64 + tI] = gv;
    }
    __syncthreads();

    float* almat = out + (has_gamma ? (size_t)BATCH * LSEQ : 0);
    int kq = tI & 63, rr = tI >> 6;
    float k0f = (float)(kq * 4);
    float* base = almat + ((size_t)b * LSEQ + (size_t)lt * 64) * KOUT + kq * 4;
    #pragma unroll 4
    for (int il = rr; il < 64; il += 4) {
        float gv = gsm[il];
        float4 v;
        v.x = fmaxf(1.f - fabsf(gv - k0f        ), 0.f);
        v.y = fmaxf(1.f - fabsf(gv - (k0f + 1.f)), 0.f);
        v.z = fmaxf(1.f - fabsf(gv - (k0f + 2.f)), 0.f);
        v.w = fmaxf(1.f - fabsf(gv - (k0f + 3.f)), 0.f);
        __stcs((float4*)(base + (size_t)il * KOUT), v);
    }
}

// =============================================================================
extern "C" void kernel_launch(void* const* d_in, const int* in_sizes, int n_in,
                              void* d_out, int out_size)
{
    const float* X    = (const float*)d_in[0];
    const float* mask = (const float*)d_in[1];
    const float* W1   = (const float*)d_in[2];
    const float* b1   = (const float*)d_in[3];
    const float* W2   = (const float*)d_in[4];
    const float* Wr   = (const float*)d_in[5];
    const float* br   = (const float*)d_in[6];
    float* out = (float*)d_out;

    cudaFuncSetAttribute(k1_attn, cudaFuncAttributeMaxDynamicSharedMemorySize,
                         SMEM_K1);

    k0_prep<<<96, 256>>>(W1, W2);
    k1_attn<<<dim3(NCHUNK, BATCH), 256, SMEM_K1>>>(X, mask, b1, Wr);
    k23<<<BATCH, 256>>>(br);

    int has_gamma =
        ((size_t)out_size >= (size_t)BATCH * LSEQ * KOUT + (size_t)BATCH * LSEQ)
            ? 1 : 0;
    k4_out<<<dim3(LSEQ / 64, BATCH), 256>>>(out, has_gamma);
}

// round 16
// speedup vs baseline: 1.3195x; 1.0689x over previous
#include <cuda_runtime.h>
#include <cuda_fp16.h>
#include <math.h>
#include <stdint.h>

// Problem constants
#define BATCH   16
#define LSEQ    4096
#define DDIM    128
#define HDIM    256
#define KA      255
#define KOUT    256
#define LCHUNK  64
#define NCHUNK  64
#define MASKVAL -1e30f

// ---------------- device scratch (no allocation allowed) --------------------
__device__ float  g_partS0[BATCH * NCHUNK * 256];
__device__ float  g_partS1[BATCH * NCHUNK * 256];
__device__ float4 g_params4[BATCH * KA * 2];
__device__ float  g_aArr[BATCH * 256];   // sorted a_k + sentinel
__device__ float  g_bArr[BATCH * 256];   // sorted b_k + sentinel
// fp16 B-fragment images, PAIRED tiles (one LDS.128 = 2 tiles):
__device__ __align__(16) uint2 g_W1h[8192];     // 64KB
__device__ __align__(16) uint2 g_W2h[16384];    // 128KB

// ---------------- helpers ----------------------------------------------------
__device__ __forceinline__ uint32_t smem_u32(const void* p) {
    uint32_t a;
    asm("{ .reg .u64 t; cvta.to.shared.u64 t, %1; cvt.u32.u64 %0, t; }"
        : "=r"(a) : "l"(p));
    return a;
}
__device__ __forceinline__ void cp16(uint32_t dst, const void* src) {
    asm volatile("cp.async.cg.shared.global [%0], [%1], 16;"
                 :: "r"(dst), "l"(src) : "memory");
}
#define CP_COMMIT() asm volatile("cp.async.commit_group;" ::: "memory")
#define CP_WAIT0()  asm volatile("cp.async.wait_group 0;" ::: "memory")

__device__ __forceinline__ uint32_t hfpack(float a, float b) {
    __half ha = __float2half_rn(a);
    __half hb = __float2half_rn(b);
    return (uint32_t)__half_as_ushort(ha) |
           ((uint32_t)__half_as_ushort(hb) << 16);
}
__device__ __forceinline__ void mma_f16(float* c, const uint4& a,
                                        uint32_t b0, uint32_t b1) {
    asm volatile(
        "mma.sync.aligned.m16n8k16.row.col.f32.f16.f16.f32 "
        "{%0,%1,%2,%3}, {%4,%5,%6,%7}, {%8,%9}, {%0,%1,%2,%3};"
        : "+f"(c[0]), "+f"(c[1]), "+f"(c[2]), "+f"(c[3])
        : "r"(a.x), "r"(a.y), "r"(a.z), "r"(a.w), "r"(b0), "r"(b1));
}
__device__ __forceinline__ float ftanh(float x) {
    float e = __expf(2.f * x);
    return 1.f - __fdividef(2.f, e + 1.f);
}

// =============================================================================
// K0: fp16 B images, PAIRED tile layout. W2 ordered for 128-col chunks.
// =============================================================================
__global__ void k0_prep(const float* __restrict__ W1, const float* __restrict__ W2)
{
    int g = blockIdx.x * 256 + threadIdx.x;
    if (g < 8192) {                 // W1 [128][256]
        int i1 = g >> 5, t = g & 31;
        int kt = i1 >> 5, ntG = i1 & 31;
        int n = ntG * 8 + (t >> 2);
        int k = kt * 16 + (t & 3) * 2;
        uint2 r;
        r.x = hfpack(W1[k * 256 + n],       W1[(k + 1) * 256 + n]);
        r.y = hfpack(W1[(k + 8) * 256 + n], W1[(k + 9) * 256 + n]);
        int p = ntG >> 1, half = ntG & 1;
        g_W1h[(kt * 16 + p) * 64 + t * 2 + half] = r;
    } else if (g < 8192 + 16384) {  // W2 [256][255] -> padded to 256 cols
        int g2 = g - 8192;
        int i2 = g2 >> 5, t = g2 & 31;
        int tile = i2;                            // 512 tiles
        int cc = tile >> 8, r2 = tile & 255;      // chunk (128 cols), 256 tiles
        int kt2 = r2 >> 4, nt2 = r2 & 15;
        int n = cc * 128 + nt2 * 8 + (t >> 2);
        int k = kt2 * 16 + (t & 3) * 2;
        float v0 = 0.f, v1 = 0.f, v2 = 0.f, v3 = 0.f;
        if (n < KA) {
            v0 = W2[k * KA + n];
            v1 = W2[(k + 1) * KA + n];
            v2 = W2[(k + 8) * KA + n];
            v3 = W2[(k + 9) * KA + n];
        }
        uint2 r;
        r.x = hfpack(v0, v1);
        r.y = hfpack(v2, v3);
        int p = nt2 >> 1, half = nt2 & 1;
        g_W2h[(cc * 128 + kt2 * 8 + p) * 64 + t * 2 + half] = r;
    }
}

// ---------------- K1 smem byte map (unchanged from R15) ----------------------
#define X_OFF    0
#define W1_OFF   16384
#define A2_OFF   0
#define W2_OFF   32768
#define RS_B     98304
#define MS_B     98560
#define BS_B     98816
#define PART_B   99840
#define SMEM_K1  104448

// =============================================================================
// K1: unchanged from R15 (64-row chunks, 2/SM; GEMM2 two 128-col chunks).
// =============================================================================
__global__ __launch_bounds__(256, 2)
void k1_attn(const float* __restrict__ X, const float* __restrict__ mask,
             const float* __restrict__ b1, const float* __restrict__ Wr)
{
    extern __shared__ char smc[];
    uint4*  Xs   = (uint4*)(smc + X_OFF);
    uint4*  W1s4 = (uint4*)(smc + W1_OFF);
    uint4*  A2s  = (uint4*)(smc + A2_OFF);
    uint4*  W2s4 = (uint4*)(smc + W2_OFF);
    float*  rsm  = (float*)(smc + RS_B);
    float*  msm  = (float*)(smc + MS_B);
    float*  bsm  = (float*)(smc + BS_B);
    float2* part = (float2*)(smc + PART_B);

    const uint32_t sb  = smem_u32(smc);
    const int tid = threadIdx.x;
    const int wid = tid >> 5;
    const int t   = tid & 31;
    const int b     = blockIdx.y;
    const int chunk = blockIdx.x;
    const int l0    = chunk * LCHUNK;

    const float* Xg = X + ((size_t)b * LSEQ + l0) * DDIM;

    {
        uint32_t dst = sb + W1_OFF;
        #pragma unroll
        for (int i = 0; i < 16; ++i)
            cp16(dst + (tid + i * 256) * 16, (const uint4*)g_W1h + tid + i * 256);
        CP_COMMIT();
    }

    {
        int mtile = wid >> 1;
        int khalf = wid & 1;
        int r0 = mtile * 16 + (t >> 2);
        const float* xr0 = Xg + r0 * DDIM;
        const float* xr1 = Xg + (r0 + 8) * DDIM;
        #pragma unroll
        for (int kq = 0; kq < 4; ++kq) {
            int kt = khalf * 4 + kq;
            int k0 = kt * 16 + (t & 3) * 2;
            float2 v00 = *(const float2*)(xr0 + k0);
            float2 v10 = *(const float2*)(xr1 + k0);
            float2 v01 = *(const float2*)(xr0 + k0 + 8);
            float2 v11 = *(const float2*)(xr1 + k0 + 8);
            uint4 hi;
            hi.x = hfpack(v00.x, v00.y);
            hi.y = hfpack(v10.x, v10.y);
            hi.z = hfpack(v01.x, v01.y);
            hi.w = hfpack(v11.x, v11.y);
            Xs[(mtile * 8 + kt) * 32 + t] = hi;
        }
    }

    if (tid < 64) {
        float s0 = 0.f, s1 = 0.f, s2 = 0.f, s3 = 0.f;
        const float4* xr = (const float4*)(Xg + tid * DDIM);
        const float4* wr = (const float4*)Wr;
        #pragma unroll 8
        for (int d = 0; d < 32; ++d) {
            float4 xv = xr[d], wv = wr[d];
            s0 = fmaf(xv.x, wv.x, s0);
            s1 = fmaf(xv.y, wv.y, s1);
            s2 = fmaf(xv.z, wv.z, s2);
            s3 = fmaf(xv.w, wv.w, s3);
        }
        rsm[tid] = (s0 + s1) + (s2 + s3);
        msm[tid] = mask[(size_t)b * LSEQ + l0 + tid];
    }
    bsm[tid] = b1[tid];
    CP_WAIT0();
    __syncthreads();

    const int warpM1 = wid & 1;
    const int warpN1 = wid >> 1;

    float acc[2][8][4];
    #pragma unroll
    for (int mt = 0; mt < 2; ++mt)
        #pragma unroll
        for (int nt = 0; nt < 8; ++nt)
            #pragma unroll
            for (int q = 0; q < 4; ++q) acc[mt][nt][q] = 0.f;

    #pragma unroll 1
    for (int kt = 0; kt < 8; ++kt) {
        uint4 ah[2];
        #pragma unroll
        for (int mt = 0; mt < 2; ++mt) {
            int mtG = warpM1 * 2 + mt;
            ah[mt] = Xs[(mtG * 8 + kt) * 32 + t];
        }
        #pragma unroll
        for (int pp = 0; pp < 4; ++pp) {
            uint4 bb = W1s4[(kt * 16 + warpN1 * 4 + pp) * 32 + t];
            #pragma unroll
            for (int mt = 0; mt < 2; ++mt) {
                mma_f16(acc[mt][pp * 2 + 0], ah[mt], bb.x, bb.y);
                mma_f16(acc[mt][pp * 2 + 1], ah[mt], bb.z, bb.w);
            }
        }
    }
    __syncthreads();

    {
        uint32_t dst = sb + W2_OFF;
        #pragma unroll
        for (int i = 0; i < 16; ++i)
            cp16(dst + (tid + i * 256) * 16, (const uint4*)g_W2h + tid + i * 256);
        CP_COMMIT();
    }

    #pragma unroll
    for (int mt = 0; mt < 2; ++mt) {
        int mtG = warpM1 * 2 + mt;
        #pragma unroll
        for (int j = 0; j < 4; ++j) {
            int nt0 = 2 * j, nt1 = 2 * j + 1;
            int c0 = (warpN1 * 8 + nt0) * 8 + (t & 3) * 2;
            int c1 = (warpN1 * 8 + nt1) * 8 + (t & 3) * 2;
            float b00 = bsm[c0], b01 = bsm[c0 + 1];
            float b10 = bsm[c1], b11 = bsm[c1 + 1];
            uint4 hi;
            hi.x = hfpack(ftanh(acc[mt][nt0][0] + b00), ftanh(acc[mt][nt0][1] + b01));
            hi.y = hfpack(ftanh(acc[mt][nt0][2] + b00), ftanh(acc[mt][nt0][3] + b01));
            hi.z = hfpack(ftanh(acc[mt][nt1][0] + b10), ftanh(acc[mt][nt1][1] + b11));
            hi.w = hfpack(ftanh(acc[mt][nt1][2] + b10), ftanh(acc[mt][nt1][3] + b11));
            int ktG = warpN1 * 4 + j;
            A2s[(mtG * 16 + ktG) * 32 + t] = hi;
        }
    }

    const int warpM = wid & 1;
    const int warpN = wid >> 1;

    float mva[2], mvb[2], rwa[2], rwb[2];
    #pragma unroll
    for (int mt = 0; mt < 2; ++mt) {
        int row = warpM * 32 + mt * 16 + (t >> 2);
        mva[mt] = msm[row];     mvb[mt] = msm[row + 8];
        rwa[mt] = rsm[row];     rwb[mt] = rsm[row + 8];
    }

    CP_WAIT0();
    __syncthreads();

    #pragma unroll 1
    for (int c = 0; c < 2; ++c) {
        if (c == 1) {
            __syncthreads();
            uint32_t dst = sb + W2_OFF;
            #pragma unroll
            for (int i = 0; i < 16; ++i)
                cp16(dst + (tid + i * 256) * 16,
                     (const uint4*)g_W2h + 4096 + tid + i * 256);
            CP_COMMIT();
            CP_WAIT0();
            __syncthreads();
        }

        float acc2[2][4][4];
        #pragma unroll
        for (int mt = 0; mt < 2; ++mt)
            #pragma unroll
            for (int nt = 0; nt < 4; ++nt)
                #pragma unroll
                for (int q = 0; q < 4; ++q) acc2[mt][nt][q] = 0.f;

        #pragma unroll 4
        for (int kt = 0; kt < 16; ++kt) {
            uint4 ah[2];
            #pragma unroll
            for (int mt = 0; mt < 2; ++mt)
                ah[mt] = A2s[((warpM * 2 + mt) * 16 + kt) * 32 + t];
            #pragma unroll
            for (int pp = 0; pp < 2; ++pp) {
                uint4 bb = W2s4[(kt * 8 + warpN * 2 + pp) * 32 + t];
                #pragma unroll
                for (int mt = 0; mt < 2; ++mt) {
                    mma_f16(acc2[mt][pp * 2 + 0], ah[mt], bb.x, bb.y);
                    mma_f16(acc2[mt][pp * 2 + 1], ah[mt], bb.z, bb.w);
                }
            }
        }

        #pragma unroll
        for (int nt = 0; nt < 4; ++nt) {
            float s0A = 0.f, s0B = 0.f, s1A = 0.f, s1B = 0.f;
            #pragma unroll
            for (int mt = 0; mt < 2; ++mt) {
                float e0 = __expf(mva[mt] * acc2[mt][nt][0] + (1.f - mva[mt]) * MASKVAL);
                float e1 = __expf(mva[mt] * acc2[mt][nt][1] + (1.f - mva[mt]) * MASKVAL);
                float e2 = __expf(mvb[mt] * acc2[mt][nt][2] + (1.f - mvb[mt]) * MASKVAL);
                float e3 = __expf(mvb[mt] * acc2[mt][nt][3] + (1.f - mvb[mt]) * MASKVAL);
                s0A += e0 + e2;
                s0B += e1 + e3;
                s1A += fmaf(e0, rwa[mt], e2 * rwb[mt]);
                s1B += fmaf(e1, rwa[mt], e3 * rwb[mt]);
            }
            #pragma unroll
            for (int o = 4; o < 32; o <<= 1) {
                s0A += __shfl_xor_sync(0xffffffffu, s0A, o);
                s0B += __shfl_xor_sync(0xffffffffu, s0B, o);
                s1A += __shfl_xor_sync(0xffffffffu, s1A, o);
                s1B += __shfl_xor_sync(0xffffffffu, s1B, o);
            }
            if (t < 4) {
                int col = c * 128 + warpN * 32 + nt * 8 + t * 2;
                part[warpM * 256 + col]     = make_float2(s0A, s1A);
                part[warpM * 256 + col + 1] = make_float2(s0B, s1B);
            }
        }
    }
    __syncthreads();

    {
        float2 p0 = part[tid];
        float2 p1 = part[256 + tid];
        size_t idx = ((size_t)b * NCHUNK + chunk) * 256 + tid;
        g_partS0[idx] = p0.x + p1.x;
        g_partS1[idx] = p0.y + p1.y;
    }
}

// =============================================================================
// K23: reduce partials -> mu; softmax+cumsum -> cdf params + sorted a/b arrays
// =============================================================================
__global__ void k23(const float* __restrict__ br)
{
    __shared__ float sm_mu[256];
    __shared__ float ws[8];
    __shared__ float bc[2];
    int b = blockIdx.x, tI = threadIdx.x;
    int lane = tI & 31, warp = tI >> 5;

    float s0 = 0.f, s1 = 0.f;
    #pragma unroll 4
    for (int c = 0; c < NCHUNK; ++c) {
        size_t idx = ((size_t)b * NCHUNK + c) * 256 + tI;
        s0 += g_partS0[idx];
        s1 += g_partS1[idx];
    }
    sm_mu[tI] = s1 / s0 + br[0];
    __syncthreads();

    float e = (tI == 0) ? 0.f : sm_mu[tI - 1];

    float m = e;
    #pragma unroll
    for (int o = 16; o; o >>= 1) m = fmaxf(m, __shfl_xor_sync(0xffffffffu, m, o));
    if (lane == 0) ws[warp] = m;
    __syncthreads();
    if (tI < 8) {
        float v = ws[tI];
        #pragma unroll
        for (int o = 4; o; o >>= 1) v = fmaxf(v, __shfl_xor_sync(0xffu, v, o));
        if (tI == 0) bc[0] = v;
    }
    __syncthreads();
    float M = bc[0];

    float p = expf(e - M);
    float s = p;
    #pragma unroll
    for (int o = 16; o; o >>= 1) s += __shfl_xor_sync(0xffffffffu, s, o);
    if (lane == 0) ws[warp] = s;
    __syncthreads();
    if (tI < 8) {
        float v = ws[tI];
        #pragma unroll
        for (int o = 4; o; o >>= 1) v += __shfl_xor_sync(0xffu, v, o);
        if (tI == 0) bc[1] = v;
    }
    __syncthreads();
    p /= bc[1];

    float v = p;
    #pragma unroll
    for (int o = 1; o < 32; o <<= 1) {
        float u = __shfl_up_sync(0xffffffffu, v, o);
        if (lane >= o) v += u;
    }
    if (lane == 31) ws[warp] = v;
    __syncthreads();
    if (warp == 0 && lane < 8) {
        float w = ws[lane];
        #pragma unroll
        for (int o = 1; o < 8; o <<= 1) {
            float u = __shfl_up_sync(0xffu, w, o);
            if (lane >= o) w += u;
        }
        ws[lane] = w;
    }
    __syncthreads();
    float cum = v + (warp ? ws[warp - 1] : 0.f);

    if (tI < KA) {
        float mode = fminf(fmaxf(cum, 1e-4f), 0.9999f);
        float a  = fminf(fmaxf(mode - 0.0625f, 0.f), 0.875f);
        float bb = a + 0.125f;
        float4 p0, p1;
        p0.x = mode;
        p0.y = a;
        p0.z = bb;
        p0.w = (mode - a) * 8.f;
        p1.x = 1.f / (mode - a);
        p1.y = (bb - mode) * 8.f;
        p1.z = 1.f / (bb - mode);
        p1.w = 0.f;
        g_params4[((size_t)b * KA + tI) * 2 + 0] = p0;
        g_params4[((size_t)b * KA + tI) * 2 + 1] = p1;
        g_aArr[b * 256 + tI] = a;
        g_bArr[b * 256 + tI] = bb;
    } else {
        g_aArr[b * 256 + tI] = 1e30f;   // sentinel
        g_bArr[b * 256 + tI] = 1e30f;
    }
}

// ---- binary prefix counts over sorted smem arrays (256 entries + sentinel) --
__device__ __forceinline__ int count_le(const float* arr, float thr) {
    int c = 0;
    #pragma unroll
    for (int s = 128; s > 0; s >>= 1)
        if (arr[c + s - 1] <= thr) c += s;
    return c;
}
__device__ __forceinline__ int count_lt(const float* arr, float thr) {
    int c = 0;
    #pragma unroll
    for (int s = 128; s > 0; s >>= 1)
        if (arr[c + s - 1] < thr) c += s;
    return c;
}

// =============================================================================
// K4: gamma via sorted-window cdf (exact: cdf=1 for x>=b_k, 0 for x<=a_k),
// then sparse-aware almat (float4 exactly zero unless g in (k0-1, k0+4)).
// 128 rows/block (2 threads per row for the window sum), grid (32, 16).
// =============================================================================
__global__ __launch_bounds__(256)
void k4_out(float* __restrict__ out, int has_gamma)
{
    __shared__ float4 P4[KA * 2];
    __shared__ float aS[256];
    __shared__ float bS[256];
    __shared__ float gsm[128];
    int b = blockIdx.y, lt = blockIdx.x, tI = threadIdx.x;

    for (int i = tI; i < KA * 2; i += 256)
        P4[i] = g_params4[(size_t)b * KA * 2 + i];
    aS[tI] = g_aArr[b * 256 + tI];
    bS[tI] = g_bArr[b * 256 + tI];
    __syncthreads();

    int row = tI >> 1, half = tI & 1;
    int l = lt * 128 + row;
    float x = (float)l * (1.0f / 4095.0f);

    int n1 = count_le(bS, x);   // cdf exactly 1
    int n2 = count_lt(aS, x);   // window end (cdf exactly 0 beyond)

    float sum = 0.f;
    for (int k = n1 + half; k < n2; k += 2) {
        float4 p0 = P4[k * 2], p1 = P4[k * 2 + 1];
        float mm = p0.x, a = p0.y, bb = p0.z, c1 = p0.w;
        float ima = p1.x, c2 = p1.y, ibm = p1.z;
        float u = __saturatef((x - a) * ima);
        float u2 = u * u, u4 = u2 * u2, u8 = u4 * u4;
        float left = c1 * (u8 * u8);
        float v = __saturatef((bb - x) * ibm);
        float v2 = v * v, v4 = v2 * v2, v8 = v4 * v4;
        float right = 1.f - c2 * (v8 * v8);
        sum += (x <= mm) ? left : right;
    }
    sum += __shfl_xor_sync(0xffffffffu, sum, 1);
    float g = (float)n1 + sum;
    if (!half) {
        gsm[row] = g;
        if (has_gamma) out[(size_t)b * LSEQ + l] = g;
    }
    __syncthreads();

    float* almat = out + (has_gamma ? (size_t)BATCH * LSEQ : 0);
    int kq = tI & 63, rr = tI >> 6;
    float k0f = (float)(kq * 4);
    const float4 zero4 = make_float4(0.f, 0.f, 0.f, 0.f);
    float* base = almat + ((size_t)b * LSEQ + (size_t)lt * 128) * KOUT + kq * 4;
    #pragma unroll 4
    for (int il = rr; il < 128; il += 4) {
        float gv = gsm[il];
        float4 v = zero4;
        if (gv > k0f - 1.f && gv < k0f + 4.f) {
            v.x = fmaxf(1.f - fabsf(gv - k0f        ), 0.f);
            v.y = fmaxf(1.f - fabsf(gv - (k0f + 1.f)), 0.f);
            v.z = fmaxf(1.f - fabsf(gv - (k0f + 2.f)), 0.f);
            v.w = fmaxf(1.f - fabsf(gv - (k0f + 3.f)), 0.f);
        }
        __stcs((float4*)(base + (size_t)il * KOUT), v);
    }
}

// =============================================================================
extern "C" void kernel_launch(void* const* d_in, const int* in_sizes, int n_in,
                              void* d_out, int out_size)
{
    const float* X    = (const float*)d_in[0];
    const float* mask = (const float*)d_in[1];
    const float* W1   = (const float*)d_in[2];
    const float* b1   = (const float*)d_in[3];
    const float* W2   = (const float*)d_in[4];
    const float* Wr   = (const float*)d_in[5];
    const float* br   = (const float*)d_in[6];
    float* out = (float*)d_out;

    cudaFuncSetAttribute(k1_attn, cudaFuncAttributeMaxDynamicSharedMemorySize,
                         SMEM_K1);

    k0_prep<<<96, 256>>>(W1, W2);
    k1_attn<<<dim3(NCHUNK, BATCH), 256, SMEM_K1>>>(X, mask, b1, Wr);
    k23<<<BATCH, 256>>>(br);

    int has_gamma =
        ((size_t)out_size >= (size_t)BATCH * LSEQ * KOUT + (size_t)BATCH * LSEQ)
            ? 1 : 0;
    k4_out<<<dim3(LSEQ / 128, BATCH), 256>>>(out, has_gamma);
}

// round 17
// speedup vs baseline: 1.3323x; 1.0097x over previous
#include <cuda_runtime.h>
#include <cuda_fp16.h>
#include <math.h>
#include <stdint.h>

// Problem constants
#define BATCH   16
#define LSEQ    4096
#define DDIM    128
#define HDIM    256
#define KA      255
#define KOUT    256
#define LCHUNK  64
#define NCHUNK  64
#define MASKVAL -1e30f

// ---------------- device scratch (no allocation allowed) --------------------
__device__ float  g_partS0[BATCH * NCHUNK * 256];
__device__ float  g_partS1[BATCH * NCHUNK * 256];
__device__ float4 g_params4[BATCH * KA * 2];
__device__ float  g_aArr[BATCH * 256];   // sorted a_k + sentinel
__device__ float  g_bArr[BATCH * 256];   // sorted b_k + sentinel
// fp16 B-fragment images, PAIRED tiles (one LDS.128 = 2 tiles):
__device__ __align__(16) uint2 g_W1h[8192];     // 64KB
__device__ __align__(16) uint2 g_W2h[16384];    // 128KB

// ---------------- helpers ----------------------------------------------------
__device__ __forceinline__ uint32_t smem_u32(const void* p) {
    uint32_t a;
    asm("{ .reg .u64 t; cvta.to.shared.u64 t, %1; cvt.u32.u64 %0, t; }"
        : "=r"(a) : "l"(p));
    return a;
}
__device__ __forceinline__ void cp16(uint32_t dst, const void* src) {
    asm volatile("cp.async.cg.shared.global [%0], [%1], 16;"
                 :: "r"(dst), "l"(src) : "memory");
}
#define CP_COMMIT() asm volatile("cp.async.commit_group;" ::: "memory")
#define CP_WAIT0()  asm volatile("cp.async.wait_group 0;" ::: "memory")

__device__ __forceinline__ uint32_t hfpack(float a, float b) {
    __half ha = __float2half_rn(a);
    __half hb = __float2half_rn(b);
    return (uint32_t)__half_as_ushort(ha) |
           ((uint32_t)__half_as_ushort(hb) << 16);
}
__device__ __forceinline__ void mma_f16(float* c, const uint4& a,
                                        uint32_t b0, uint32_t b1) {
    asm volatile(
        "mma.sync.aligned.m16n8k16.row.col.f32.f16.f16.f32 "
        "{%0,%1,%2,%3}, {%4,%5,%6,%7}, {%8,%9}, {%0,%1,%2,%3};"
        : "+f"(c[0]), "+f"(c[1]), "+f"(c[2]), "+f"(c[3])
        : "r"(a.x), "r"(a.y), "r"(a.z), "r"(a.w), "r"(b0), "r"(b1));
}
__device__ __forceinline__ float ftanh(float x) {
    float e = __expf(2.f * x);
    return 1.f - __fdividef(2.f, e + 1.f);
}

// =============================================================================
// K0: fp16 B images, PAIRED tile layout. W2 ordered for 128-col chunks.
// =============================================================================
__global__ void k0_prep(const float* __restrict__ W1, const float* __restrict__ W2)
{
    int g = blockIdx.x * 256 + threadIdx.x;
    if (g < 8192) {                 // W1 [128][256]
        int i1 = g >> 5, t = g & 31;
        int kt = i1 >> 5, ntG = i1 & 31;
        int n = ntG * 8 + (t >> 2);
        int k = kt * 16 + (t & 3) * 2;
        uint2 r;
        r.x = hfpack(W1[k * 256 + n],       W1[(k + 1) * 256 + n]);
        r.y = hfpack(W1[(k + 8) * 256 + n], W1[(k + 9) * 256 + n]);
        int p = ntG >> 1, half = ntG & 1;
        g_W1h[(kt * 16 + p) * 64 + t * 2 + half] = r;
    } else if (g < 8192 + 16384) {  // W2 [256][255] -> padded to 256 cols
        int g2 = g - 8192;
        int i2 = g2 >> 5, t = g2 & 31;
        int tile = i2;                            // 512 tiles
        int cc = tile >> 8, r2 = tile & 255;      // chunk (128 cols), 256 tiles
        int kt2 = r2 >> 4, nt2 = r2 & 15;
        int n = cc * 128 + nt2 * 8 + (t >> 2);
        int k = kt2 * 16 + (t & 3) * 2;
        float v0 = 0.f, v1 = 0.f, v2 = 0.f, v3 = 0.f;
        if (n < KA) {
            v0 = W2[k * KA + n];
            v1 = W2[(k + 1) * KA + n];
            v2 = W2[(k + 8) * KA + n];
            v3 = W2[(k + 9) * KA + n];
        }
        uint2 r;
        r.x = hfpack(v0, v1);
        r.y = hfpack(v2, v3);
        int p = nt2 >> 1, half = nt2 & 1;
        g_W2h[(cc * 128 + kt2 * 8 + p) * 64 + t * 2 + half] = r;
    }
}

// ---------------- K1 smem byte map (unchanged from R15) ----------------------
#define X_OFF    0
#define W1_OFF   16384
#define A2_OFF   0
#define W2_OFF   32768
#define RS_B     98304
#define MS_B     98560
#define BS_B     98816
#define PART_B   99840
#define SMEM_K1  104448

// =============================================================================
// K1: unchanged from R15 (64-row chunks, 2/SM; GEMM2 two 128-col chunks).
// =============================================================================
__global__ __launch_bounds__(256, 2)
void k1_attn(const float* __restrict__ X, const float* __restrict__ mask,
             const float* __restrict__ b1, const float* __restrict__ Wr)
{
    extern __shared__ char smc[];
    uint4*  Xs   = (uint4*)(smc + X_OFF);
    uint4*  W1s4 = (uint4*)(smc + W1_OFF);
    uint4*  A2s  = (uint4*)(smc + A2_OFF);
    uint4*  W2s4 = (uint4*)(smc + W2_OFF);
    float*  rsm  = (float*)(smc + RS_B);
    float*  msm  = (float*)(smc + MS_B);
    float*  bsm  = (float*)(smc + BS_B);
    float2* part = (float2*)(smc + PART_B);

    const uint32_t sb  = smem_u32(smc);
    const int tid = threadIdx.x;
    const int wid = tid >> 5;
    const int t   = tid & 31;
    const int b     = blockIdx.y;
    const int chunk = blockIdx.x;
    const int l0    = chunk * LCHUNK;

    const float* Xg = X + ((size_t)b * LSEQ + l0) * DDIM;

    {
        uint32_t dst = sb + W1_OFF;
        #pragma unroll
        for (int i = 0; i < 16; ++i)
            cp16(dst + (tid + i * 256) * 16, (const uint4*)g_W1h + tid + i * 256);
        CP_COMMIT();
    }

    {
        int mtile = wid >> 1;
        int khalf = wid & 1;
        int r0 = mtile * 16 + (t >> 2);
        const float* xr0 = Xg + r0 * DDIM;
        const float* xr1 = Xg + (r0 + 8) * DDIM;
        #pragma unroll
        for (int kq = 0; kq < 4; ++kq) {
            int kt = khalf * 4 + kq;
            int k0 = kt * 16 + (t & 3) * 2;
            float2 v00 = *(const float2*)(xr0 + k0);
            float2 v10 = *(const float2*)(xr1 + k0);
            float2 v01 = *(const float2*)(xr0 + k0 + 8);
            float2 v11 = *(const float2*)(xr1 + k0 + 8);
            uint4 hi;
            hi.x = hfpack(v00.x, v00.y);
            hi.y = hfpack(v10.x, v10.y);
            hi.z = hfpack(v01.x, v01.y);
            hi.w = hfpack(v11.x, v11.y);
            Xs[(mtile * 8 + kt) * 32 + t] = hi;
        }
    }

    if (tid < 64) {
        float s0 = 0.f, s1 = 0.f, s2 = 0.f, s3 = 0.f;
        const float4* xr = (const float4*)(Xg + tid * DDIM);
        const float4* wr = (const float4*)Wr;
        #pragma unroll 8
        for (int d = 0; d < 32; ++d) {
            float4 xv = xr[d], wv = wr[d];
            s0 = fmaf(xv.x, wv.x, s0);
            s1 = fmaf(xv.y, wv.y, s1);
            s2 = fmaf(xv.z, wv.z, s2);
            s3 = fmaf(xv.w, wv.w, s3);
        }
        rsm[tid] = (s0 + s1) + (s2 + s3);
        msm[tid] = mask[(size_t)b * LSEQ + l0 + tid];
    }
    bsm[tid] = b1[tid];
    CP_WAIT0();
    __syncthreads();

    const int warpM1 = wid & 1;
    const int warpN1 = wid >> 1;

    float acc[2][8][4];
    #pragma unroll
    for (int mt = 0; mt < 2; ++mt)
        #pragma unroll
        for (int nt = 0; nt < 8; ++nt)
            #pragma unroll
            for (int q = 0; q < 4; ++q) acc[mt][nt][q] = 0.f;

    #pragma unroll 1
    for (int kt = 0; kt < 8; ++kt) {
        uint4 ah[2];
        #pragma unroll
        for (int mt = 0; mt < 2; ++mt) {
            int mtG = warpM1 * 2 + mt;
            ah[mt] = Xs[(mtG * 8 + kt) * 32 + t];
        }
        #pragma unroll
        for (int pp = 0; pp < 4; ++pp) {
            uint4 bb = W1s4[(kt * 16 + warpN1 * 4 + pp) * 32 + t];
            #pragma unroll
            for (int mt = 0; mt < 2; ++mt) {
                mma_f16(acc[mt][pp * 2 + 0], ah[mt], bb.x, bb.y);
                mma_f16(acc[mt][pp * 2 + 1], ah[mt], bb.z, bb.w);
            }
        }
    }
    __syncthreads();

    {
        uint32_t dst = sb + W2_OFF;
        #pragma unroll
        for (int i = 0; i < 16; ++i)
            cp16(dst + (tid + i * 256) * 16, (const uint4*)g_W2h + tid + i * 256);
        CP_COMMIT();
    }

    #pragma unroll
    for (int mt = 0; mt < 2; ++mt) {
        int mtG = warpM1 * 2 + mt;
        #pragma unroll
        for (int j = 0; j < 4; ++j) {
            int nt0 = 2 * j, nt1 = 2 * j + 1;
            int c0 = (warpN1 * 8 + nt0) * 8 + (t & 3) * 2;
            int c1 = (warpN1 * 8 + nt1) * 8 + (t & 3) * 2;
            float b00 = bsm[c0], b01 = bsm[c0 + 1];
            float b10 = bsm[c1], b11 = bsm[c1 + 1];
            uint4 hi;
            hi.x = hfpack(ftanh(acc[mt][nt0][0] + b00), ftanh(acc[mt][nt0][1] + b01));
            hi.y = hfpack(ftanh(acc[mt][nt0][2] + b00), ftanh(acc[mt][nt0][3] + b01));
            hi.z = hfpack(ftanh(acc[mt][nt1][0] + b10), ftanh(acc[mt][nt1][1] + b11));
            hi.w = hfpack(ftanh(acc[mt][nt1][2] + b10), ftanh(acc[mt][nt1][3] + b11));
            int ktG = warpN1 * 4 + j;
            A2s[(mtG * 16 + ktG) * 32 + t] = hi;
        }
    }

    const int warpM = wid & 1;
    const int warpN = wid >> 1;

    float mva[2], mvb[2], rwa[2], rwb[2];
    #pragma unroll
    for (int mt = 0; mt < 2; ++mt) {
        int row = warpM * 32 + mt * 16 + (t >> 2);
        mva[mt] = msm[row];     mvb[mt] = msm[row + 8];
        rwa[mt] = rsm[row];     rwb[mt] = rsm[row + 8];
    }

    CP_WAIT0();
    __syncthreads();

    #pragma unroll 1
    for (int c = 0; c < 2; ++c) {
        if (c == 1) {
            __syncthreads();
            uint32_t dst = sb + W2_OFF;
            #pragma unroll
            for (int i = 0; i < 16; ++i)
                cp16(dst + (tid + i * 256) * 16,
                     (const uint4*)g_W2h + 4096 + tid + i * 256);
            CP_COMMIT();
            CP_WAIT0();
            __syncthreads();
        }

        float acc2[2][4][4];
        #pragma unroll
        for (int mt = 0; mt < 2; ++mt)
            #pragma unroll
            for (int nt = 0; nt < 4; ++nt)
                #pragma unroll
                for (int q = 0; q < 4; ++q) acc2[mt][nt][q] = 0.f;

        #pragma unroll 4
        for (int kt = 0; kt < 16; ++kt) {
            uint4 ah[2];
            #pragma unroll
            for (int mt = 0; mt < 2; ++mt)
                ah[mt] = A2s[((warpM * 2 + mt) * 16 + kt) * 32 + t];
            #pragma unroll
            for (int pp = 0; pp < 2; ++pp) {
                uint4 bb = W2s4[(kt * 8 + warpN * 2 + pp) * 32 + t];
                #pragma unroll
                for (int mt = 0; mt < 2; ++mt) {
                    mma_f16(acc2[mt][pp * 2 + 0], ah[mt], bb.x, bb.y);
                    mma_f16(acc2[mt][pp * 2 + 1], ah[mt], bb.z, bb.w);
                }
            }
        }

        #pragma unroll
        for (int nt = 0; nt < 4; ++nt) {
            float s0A = 0.f, s0B = 0.f, s1A = 0.f, s1B = 0.f;
            #pragma unroll
            for (int mt = 0; mt < 2; ++mt) {
                float e0 = __expf(mva[mt] * acc2[mt][nt][0] + (1.f - mva[mt]) * MASKVAL);
                float e1 = __expf(mva[mt] * acc2[mt][nt][1] + (1.f - mva[mt]) * MASKVAL);
                float e2 = __expf(mvb[mt] * acc2[mt][nt][2] + (1.f - mvb[mt]) * MASKVAL);
                float e3 = __expf(mvb[mt] * acc2[mt][nt][3] + (1.f - mvb[mt]) * MASKVAL);
                s0A += e0 + e2;
                s0B += e1 + e3;
                s1A += fmaf(e0, rwa[mt], e2 * rwb[mt]);
                s1B += fmaf(e1, rwa[mt], e3 * rwb[mt]);
            }
            #pragma unroll
            for (int o = 4; o < 32; o <<= 1) {
                s0A += __shfl_xor_sync(0xffffffffu, s0A, o);
                s0B += __shfl_xor_sync(0xffffffffu, s0B, o);
                s1A += __shfl_xor_sync(0xffffffffu, s1A, o);
                s1B += __shfl_xor_sync(0xffffffffu, s1B, o);
            }
            if (t < 4) {
                int col = c * 128 + warpN * 32 + nt * 8 + t * 2;
                part[warpM * 256 + col]     = make_float2(s0A, s1A);
                part[warpM * 256 + col + 1] = make_float2(s0B, s1B);
            }
        }
    }
    __syncthreads();

    {
        float2 p0 = part[tid];
        float2 p1 = part[256 + tid];
        size_t idx = ((size_t)b * NCHUNK + chunk) * 256 + tid;
        g_partS0[idx] = p0.x + p1.x;
        g_partS1[idx] = p0.y + p1.y;
    }
}

// =============================================================================
// K23: reduce partials -> mu; softmax+cumsum -> cdf params + sorted a/b arrays
// =============================================================================
__global__ void k23(const float* __restrict__ br)
{
    __shared__ float sm_mu[256];
    __shared__ float ws[8];
    __shared__ float bc[2];
    int b = blockIdx.x, tI = threadIdx.x;
    int lane = tI & 31, warp = tI >> 5;

    float s0 = 0.f, s1 = 0.f;
    #pragma unroll 4
    for (int c = 0; c < NCHUNK; ++c) {
        size_t idx = ((size_t)b * NCHUNK + c) * 256 + tI;
        s0 += g_partS0[idx];
        s1 += g_partS1[idx];
    }
    sm_mu[tI] = s1 / s0 + br[0];
    __syncthreads();

    float e = (tI == 0) ? 0.f : sm_mu[tI - 1];

    float m = e;
    #pragma unroll
    for (int o = 16; o; o >>= 1) m = fmaxf(m, __shfl_xor_sync(0xffffffffu, m, o));
    if (lane == 0) ws[warp] = m;
    __syncthreads();
    if (tI < 8) {
        float v = ws[tI];
        #pragma unroll
        for (int o = 4; o; o >>= 1) v = fmaxf(v, __shfl_xor_sync(0xffu, v, o));
        if (tI == 0) bc[0] = v;
    }
    __syncthreads();
    float M = bc[0];

    float p = expf(e - M);
    float s = p;
    #pragma unroll
    for (int o = 16; o; o >>= 1) s += __shfl_xor_sync(0xffffffffu, s, o);
    if (lane == 0) ws[warp] = s;
    __syncthreads();
    if (tI < 8) {
        float v = ws[tI];
        #pragma unroll
        for (int o = 4; o; o >>= 1) v += __shfl_xor_sync(0xffu, v, o);
        if (tI == 0) bc[1] = v;
    }
    __syncthreads();
    p /= bc[1];

    float v = p;
    #pragma unroll
    for (int o = 1; o < 32; o <<= 1) {
        float u = __shfl_up_sync(0xffffffffu, v, o);
        if (lane >= o) v += u;
    }
    if (lane == 31) ws[warp] = v;
    __syncthreads();
    if (warp == 0 && lane < 8) {
        float w = ws[lane];
        #pragma unroll
        for (int o = 1; o < 8; o <<= 1) {
            float u = __shfl_up_sync(0xffu, w, o);
            if (lane >= o) w += u;
        }
        ws[lane] = w;
    }
    __syncthreads();
    float cum = v + (warp ? ws[warp - 1] : 0.f);

    if (tI < KA) {
        float mode = fminf(fmaxf(cum, 1e-4f), 0.9999f);
        float a  = fminf(fmaxf(mode - 0.0625f, 0.f), 0.875f);
        float bb = a + 0.125f;
        float4 p0, p1;
        p0.x = mode;
        p0.y = a;
        p0.z = bb;
        p0.w = (mode - a) * 8.f;
        p1.x = 1.f / (mode - a);
        p1.y = (bb - mode) * 8.f;
        p1.z = 1.f / (bb - mode);
        p1.w = 0.f;
        g_params4[((size_t)b * KA + tI) * 2 + 0] = p0;
        g_params4[((size_t)b * KA + tI) * 2 + 1] = p1;
        g_aArr[b * 256 + tI] = a;
        g_bArr[b * 256 + tI] = bb;
    } else {
        g_aArr[b * 256 + tI] = 1e30f;   // sentinel
        g_bArr[b * 256 + tI] = 1e30f;
    }
}

// ---- binary prefix counts over sorted smem arrays (256 entries + sentinel) --
__device__ __forceinline__ int count_le(const float* arr, float thr) {
    int c = 0;
    #pragma unroll
    for (int s = 128; s > 0; s >>= 1)
        if (arr[c + s - 1] <= thr) c += s;
    return c;
}
__device__ __forceinline__ int count_lt(const float* arr, float thr) {
    int c = 0;
    #pragma unroll
    for (int s = 128; s > 0; s >>= 1)
        if (arr[c + s - 1] < thr) c += s;
    return c;
}

// =============================================================================
// K4: 64-row tiles (grid 1024 -> ~7 blocks/SM; the 64MB store stream was
// concurrency-starved at grid 512). Gamma via sorted-window cdf (4 threads
// per row), then zero-skip almat with streaming stores.
// =============================================================================
__global__ __launch_bounds__(256)
void k4_out(float* __restrict__ out, int has_gamma)
{
    __shared__ float4 P4[KA * 2];
    __shared__ float aS[256];
    __shared__ float bS[256];
    __shared__ float gsm[64];
    int b = blockIdx.y, lt = blockIdx.x, tI = threadIdx.x;

    for (int i = tI; i < KA * 2; i += 256)
        P4[i] = g_params4[(size_t)b * KA * 2 + i];
    aS[tI] = g_aArr[b * 256 + tI];
    bS[tI] = g_bArr[b * 256 + tI];
    __syncthreads();

    int row = tI >> 2, quad = tI & 3;
    int l = lt * 64 + row;
    float x = (float)l * (1.0f / 4095.0f);

    int n1 = count_le(bS, x);   // cdf exactly 1
    int n2 = count_lt(aS, x);   // window end (cdf exactly 0 beyond)

    float sum = 0.f;
    for (int k = n1 + quad; k < n2; k += 4) {
        float4 p0 = P4[k * 2], p1 = P4[k * 2 + 1];
        float mm = p0.x, a = p0.y, bb = p0.z, c1 = p0.w;
        float ima = p1.x, c2 = p1.y, ibm = p1.z;
        float u = __saturatef((x - a) * ima);
        float u2 = u * u, u4 = u2 * u2, u8 = u4 * u4;
        float left = c1 * (u8 * u8);
        float v = __saturatef((bb - x) * ibm);
        float v2 = v * v, v4 = v2 * v2, v8 = v4 * v4;
        float right = 1.f - c2 * (v8 * v8);
        sum += (x <= mm) ? left : right;
    }
    sum += __shfl_xor_sync(0xffffffffu, sum, 1);
    sum += __shfl_xor_sync(0xffffffffu, sum, 2);
    float g = (float)n1 + sum;
    if (quad == 0) {
        gsm[row] = g;
        if (has_gamma) out[(size_t)b * LSEQ + l] = g;
    }
    __syncthreads();

    float* almat = out + (has_gamma ? (size_t)BATCH * LSEQ : 0);
    int kq = tI & 63, rr = tI >> 6;
    float k0f = (float)(kq * 4);
    const float4 zero4 = make_float4(0.f, 0.f, 0.f, 0.f);
    float* base = almat + ((size_t)b * LSEQ + (size_t)lt * 64) * KOUT + kq * 4;
    #pragma unroll 4
    for (int il = rr; il < 64; il += 4) {
        float gv = gsm[il];
        float4 v = zero4;
        if (gv > k0f - 1.f && gv < k0f + 4.f) {
            v.x = fmaxf(1.f - fabsf(gv - k0f        ), 0.f);
            v.y = fmaxf(1.f - fabsf(gv - (k0f + 1.f)), 0.f);
            v.z = fmaxf(1.f - fabsf(gv - (k0f + 2.f)), 0.f);
            v.w = fmaxf(1.f - fabsf(gv - (k0f + 3.f)), 0.f);
        }
        __stcs((float4*)(base + (size_t)il * KOUT), v);
    }
}

// =============================================================================
extern "C" void kernel_launch(void* const* d_in, const int* in_sizes, int n_in,
                              void* d_out, int out_size)
{
    const float* X    = (const float*)d_in[0];
    const float* mask = (const float*)d_in[1];
    const float* W1   = (const float*)d_in[2];
    const float* b1   = (const float*)d_in[3];
    const float* W2   = (const float*)d_in[4];
    const float* Wr   = (const float*)d_in[5];
    const float* br   = (const float*)d_in[6];
    float* out = (float*)d_out;

    cudaFuncSetAttribute(k1_attn, cudaFuncAttributeMaxDynamicSharedMemorySize,
                         SMEM_K1);

    k0_prep<<<96, 256>>>(W1, W2);
    k1_attn<<<dim3(NCHUNK, BATCH), 256, SMEM_K1>>>(X, mask, b1, Wr);
    k23<<<BATCH, 256>>>(br);

    int has_gamma =
        ((size_t)out_size >= (size_t)BATCH * LSEQ * KOUT + (size_t)BATCH * LSEQ)
            ? 1 : 0;
    k4_out<<<dim3(LSEQ / 64, BATCH), 256>>>(out, has_gamma);
}